// round 10
// baseline (speedup 1.0000x reference)
#include <cuda_runtime.h>
#include <cuda_bf16.h>
#include <math.h>
#include <stdint.h>

// Problem dims (fixed)
#define B_  4
#define S_  2048
#define E_  2048
#define H_  16
#define D_  128
#define F_  8192
#define NTOK (B_ * S_)
#define QKV_STRIDE (3 * E_)

// ---------------------------------------------------------------------------
// Scratch (device globals)
// ---------------------------------------------------------------------------
#define WOFF_QKV 0u
#define WOFF_PROJ 12582912u               // 6144*2048
#define WOFF_FC   16777216u               // + 2048*2048
#define WOFF_MLP  33554432u               // + 2048*8192
#define WTOT      50331648u               // + 8192*2048
__device__ __nv_bfloat16 g_wt_hi[WTOT];
__device__ __nv_bfloat16 g_wt_lo[WTOT];
// Activation hi/lo planes [8192 x 2048] (ln1 -> ctx -> ln2)
__device__ __nv_bfloat16 g_act_hi[(size_t)NTOK * E_];
__device__ __nv_bfloat16 g_act_lo[(size_t)NTOK * E_];
// Large planes [8192 x 8192]; also alias qkv planes [8192 x 6144]
__device__ __nv_bfloat16 g_fc_hi[(size_t)NTOK * F_];
__device__ __nv_bfloat16 g_fc_lo[(size_t)NTOK * F_];

// ---------------------------------------------------------------------------
// PTX helpers (portable sm_80+ subset only)
// ---------------------------------------------------------------------------
__device__ __forceinline__ uint32_t smem_to_u32(const void* p) {
    uint32_t a;
    asm("{ .reg .u64 t; cvta.to.shared.u64 t, %1; cvt.u32.u64 %0, t; }" : "=r"(a) : "l"(p));
    return a;
}
__device__ __forceinline__ void cpa16(uint32_t dst, const void* src) {
    asm volatile("cp.async.cg.shared.global [%0], [%1], 16;" :: "r"(dst), "l"(src) : "memory");
}
#define CP_COMMIT() asm volatile("cp.async.commit_group;" ::: "memory")

__device__ __forceinline__ void ldsm4(uint32_t& r0, uint32_t& r1, uint32_t& r2, uint32_t& r3,
                                      uint32_t a) {
    asm volatile("ldmatrix.sync.aligned.m8n8.x4.shared.b16 {%0,%1,%2,%3}, [%4];"
                 : "=r"(r0), "=r"(r1), "=r"(r2), "=r"(r3) : "r"(a));
}
__device__ __forceinline__ void ldsm4t(uint32_t& r0, uint32_t& r1, uint32_t& r2, uint32_t& r3,
                                       uint32_t a) {
    asm volatile("ldmatrix.sync.aligned.m8n8.x4.trans.shared.b16 {%0,%1,%2,%3}, [%4];"
                 : "=r"(r0), "=r"(r1), "=r"(r2), "=r"(r3) : "r"(a));
}
__device__ __forceinline__ void mma16816(float* c, const uint32_t* a, const uint32_t* b) {
    asm volatile(
        "mma.sync.aligned.m16n8k16.row.col.f32.bf16.bf16.f32 "
        "{%0,%1,%2,%3}, {%4,%5,%6,%7}, {%8,%9}, {%0,%1,%2,%3};"
        : "+f"(c[0]), "+f"(c[1]), "+f"(c[2]), "+f"(c[3])
        : "r"(a[0]), "r"(a[1]), "r"(a[2]), "r"(a[3]), "r"(b[0]), "r"(b[1]));
}

__device__ __forceinline__ void split2_store(float a, float b,
                                             __nv_bfloat16* hp, __nv_bfloat16* lp, size_t idx) {
    __nv_bfloat16 ha = __float2bfloat16(a);
    __nv_bfloat16 hb = __float2bfloat16(b);
    __nv_bfloat16 la = __float2bfloat16(a - __bfloat162float(ha));
    __nv_bfloat16 lb = __float2bfloat16(b - __bfloat162float(hb));
    __nv_bfloat162 h2; h2.x = ha; h2.y = hb;
    __nv_bfloat162 l2; l2.x = la; l2.y = lb;
    *(__nv_bfloat162*)(hp + idx) = h2;
    *(__nv_bfloat162*)(lp + idx) = l2;
}
__device__ __forceinline__ void splitpack(float a, float b, uint32_t& hi, uint32_t& lo) {
    __nv_bfloat16 ha = __float2bfloat16(a);
    __nv_bfloat16 hb = __float2bfloat16(b);
    __nv_bfloat16 la = __float2bfloat16(a - __bfloat162float(ha));
    __nv_bfloat16 lb = __float2bfloat16(b - __bfloat162float(hb));
    hi = (uint32_t)__bfloat16_as_ushort(ha) | ((uint32_t)__bfloat16_as_ushort(hb) << 16);
    lo = (uint32_t)__bfloat16_as_ushort(la) | ((uint32_t)__bfloat16_as_ushort(lb) << 16);
}

// ---------------------------------------------------------------------------
// Weight prep: W[K,N] fp32 -> Th/Tl[N,K] bf16 (transpose + split)
// ---------------------------------------------------------------------------
__global__ __launch_bounds__(256) void wsplit_t_kernel(
    const float* __restrict__ W, __nv_bfloat16* __restrict__ Th,
    __nv_bfloat16* __restrict__ Tl, int K, int N)
{
    __shared__ float s[32][33];
    int n0 = blockIdx.x * 32, k0 = blockIdx.y * 32;
    int tx = threadIdx.x, ty = threadIdx.y;
#pragma unroll
    for (int j = 0; j < 4; j++)
        s[ty + j * 8][tx] = W[(size_t)(k0 + ty + j * 8) * N + n0 + tx];
    __syncthreads();
#pragma unroll
    for (int j = 0; j < 4; j++) {
        float v = s[tx][ty + j * 8];
        __nv_bfloat16 h = __float2bfloat16(v);
        __nv_bfloat16 l = __float2bfloat16(v - __bfloat162float(h));
        size_t o = (size_t)(n0 + ty + j * 8) * K + k0 + tx;
        Th[o] = h; Tl[o] = l;
    }
}

// ---------------------------------------------------------------------------
// Block reduction (256 threads)
// ---------------------------------------------------------------------------
__device__ __forceinline__ float blk_reduce_sum(float v, float* sbuf) {
    int lane = threadIdx.x & 31, wid = threadIdx.x >> 5;
#pragma unroll
    for (int o = 16; o; o >>= 1) v += __shfl_xor_sync(0xffffffffu, v, o);
    if (lane == 0) sbuf[wid] = v;
    __syncthreads();
    if (threadIdx.x < 32) {
        float u = (threadIdx.x < 8) ? sbuf[threadIdx.x] : 0.f;
#pragma unroll
        for (int o = 4; o; o >>= 1) u += __shfl_xor_sync(0xffffffffu, u, o);
        if (threadIdx.x == 0) sbuf[0] = u;
    }
    __syncthreads();
    float r = sbuf[0];
    __syncthreads();
    return r;
}

// ---------------------------------------------------------------------------
// LayerNorm -> bf16 hi/lo planes
// ---------------------------------------------------------------------------
__global__ __launch_bounds__(256) void ln_kernel(
    const float* __restrict__ x, const float* __restrict__ w,
    const float* __restrict__ b, __nv_bfloat16* __restrict__ oh,
    __nv_bfloat16* __restrict__ ol)
{
    __shared__ float sbuf[8];
    size_t base = (size_t)blockIdx.x * E_;
    int t = threadIdx.x;

    float4 v0 = *(const float4*)(x + base + 4 * t);
    float4 v1 = *(const float4*)(x + base + 4 * t + 1024);
    float s = v0.x + v0.y + v0.z + v0.w + v1.x + v1.y + v1.z + v1.w;
    float mean = blk_reduce_sum(s, sbuf) * (1.f / E_);
    float d, sq = 0.f;
    d = v0.x - mean; sq += d * d;  d = v0.y - mean; sq += d * d;
    d = v0.z - mean; sq += d * d;  d = v0.w - mean; sq += d * d;
    d = v1.x - mean; sq += d * d;  d = v1.y - mean; sq += d * d;
    d = v1.z - mean; sq += d * d;  d = v1.w - mean; sq += d * d;
    float var = blk_reduce_sum(sq, sbuf) * (1.f / E_);
    float r = rsqrtf(var + 1e-5f);

    float4 w0 = *(const float4*)(w + 4 * t);
    float4 w1 = *(const float4*)(w + 4 * t + 1024);
    float4 b0 = *(const float4*)(b + 4 * t);
    float4 b1 = *(const float4*)(b + 4 * t + 1024);

    float o0x = (v0.x - mean) * r * w0.x + b0.x;
    float o0y = (v0.y - mean) * r * w0.y + b0.y;
    float o0z = (v0.z - mean) * r * w0.z + b0.z;
    float o0w = (v0.w - mean) * r * w0.w + b0.w;
    float o1x = (v1.x - mean) * r * w1.x + b1.x;
    float o1y = (v1.y - mean) * r * w1.y + b1.y;
    float o1z = (v1.z - mean) * r * w1.z + b1.z;
    float o1w = (v1.w - mean) * r * w1.w + b1.w;

    split2_store(o0x, o0y, oh, ol, base + 4 * t);
    split2_store(o0z, o0w, oh, ol, base + 4 * t + 2);
    split2_store(o1x, o1y, oh, ol, base + 4 * t + 1024);
    split2_store(o1z, o1w, oh, ol, base + 4 * t + 1026);
}

// ---------------------------------------------------------------------------
// HMMA GEMM: 512 threads, 4x4 warp grid, warp tile 32x32. CTA 128x128, BK=32,
// 3-stage cp.async pipeline. 3-term bf16 split.
// ---------------------------------------------------------------------------
#define EPI_QKV   0
#define EPI_GELU  1
#define EPI_RES   2
#define EPI_SPLIT 3

#define BM 128
#define BN 128
#define BK 32
#define ROWB 80
#define SA_H 0
#define SA_L 10240
#define SB_H 20480
#define SB_L 30720
#define STAGE_BYTES 40960
#define HMMA_SMEM (3 * STAGE_BYTES)

__device__ __forceinline__ float gelu_tanh(float x) {
    float x3 = x * x * x;
    float t = tanhf(0.7978845608028654f * (x + 0.044715f * x3));
    return 0.5f * x * (1.f + t);
}

__device__ __forceinline__ void g2s_stage(
    uint32_t sb, const __nv_bfloat16* __restrict__ Ah, const __nv_bfloat16* __restrict__ Al,
    const __nv_bfloat16* __restrict__ Bh, const __nv_bfloat16* __restrict__ Bl,
    int bm, int bn, int K, int k0, int tid)
{
    // 512 threads x 1 chunk: row = tid>>2 (0..127), ch = tid&3
    int row = tid >> 2, ch = tid & 3;
    uint32_t off = (uint32_t)row * ROWB + ch * 16;
    size_t ga = (size_t)(bm + row) * K + k0 + ch * 8;
    size_t gb = (size_t)(bn + row) * K + k0 + ch * 8;
    cpa16(sb + SA_H + off, Ah + ga);
    cpa16(sb + SA_L + off, Al + ga);
    cpa16(sb + SB_H + off, Bh + gb);
    cpa16(sb + SB_L + off, Bl + gb);
    CP_COMMIT();
}

template <int EPI>
__global__ __launch_bounds__(512, 1) void hmma_kernel(
    const __nv_bfloat16* __restrict__ Ah, const __nv_bfloat16* __restrict__ Al,
    const __nv_bfloat16* __restrict__ Bh, const __nv_bfloat16* __restrict__ Bl,
    const float* __restrict__ bias, const float* __restrict__ res,
    float* __restrict__ Cf, __nv_bfloat16* __restrict__ Chi,
    __nv_bfloat16* __restrict__ Clo, int M, int N, int K)
{
    extern __shared__ char smem[];
    uint32_t sb0 = smem_to_u32(smem);
    int tid = threadIdx.x;
    int wid = tid >> 5, lane = tid & 31;
    int wm = (wid & 3) * 32, wn = (wid >> 2) * 32;
    int bm = blockIdx.y * BM, bn = blockIdx.x * BN;

    float acc[2][4][4];
#pragma unroll
    for (int i = 0; i < 2; i++)
#pragma unroll
        for (int j = 0; j < 4; j++)
#pragma unroll
            for (int k = 0; k < 4; k++) acc[i][j][k] = 0.f;

    uint32_t a_off = (uint32_t)(wm + (lane & 15)) * ROWB + ((lane >> 4) * 16);
    uint32_t b_off = (uint32_t)(wn + (lane & 7) + ((lane >> 4) * 8)) * ROWB
                   + (((lane >> 3) & 1) * 16);

    g2s_stage(sb0,               Ah, Al, Bh, Bl, bm, bn, K, 0,  tid);
    g2s_stage(sb0 + STAGE_BYTES, Ah, Al, Bh, Bl, bm, bn, K, BK, tid);

    int nk = K / BK;
    for (int kt = 0; kt < nk; kt++) {
        asm volatile("cp.async.wait_group 1;" ::: "memory");
        __syncthreads();
        if (kt + 2 < nk)
            g2s_stage(sb0 + (uint32_t)((kt + 2) % 3) * STAGE_BYTES,
                      Ah, Al, Bh, Bl, bm, bn, K, (kt + 2) * BK, tid);
        else
            CP_COMMIT();

        uint32_t st = sb0 + (uint32_t)(kt % 3) * STAGE_BYTES;
#pragma unroll
        for (int ks = 0; ks < 2; ks++) {
            uint32_t koff = (uint32_t)ks * 32;
            uint32_t ah[2][4], al[2][4];
#pragma unroll
            for (int mi = 0; mi < 2; mi++) {
                uint32_t ra = st + SA_H + a_off + (uint32_t)mi * (16 * ROWB) + koff;
                ldsm4(ah[mi][0], ah[mi][1], ah[mi][2], ah[mi][3], ra);
                ldsm4(al[mi][0], al[mi][1], al[mi][2], al[mi][3], ra + (SA_L - SA_H));
            }
            uint32_t bh[2][4], bl[2][4];
#pragma unroll
            for (int ng = 0; ng < 2; ng++) {
                uint32_t rb = st + SB_H + b_off + (uint32_t)ng * (16 * ROWB) + koff;
                ldsm4(bh[ng][0], bh[ng][1], bh[ng][2], bh[ng][3], rb);
                ldsm4(bl[ng][0], bl[ng][1], bl[ng][2], bl[ng][3], rb + (SB_L - SB_H));
            }
#pragma unroll
            for (int mi = 0; mi < 2; mi++)
#pragma unroll
                for (int nf = 0; nf < 4; nf++) {
                    const uint32_t* B0 = &bh[nf >> 1][(nf & 1) * 2];
                    const uint32_t* B1 = &bl[nf >> 1][(nf & 1) * 2];
                    mma16816(acc[mi][nf], ah[mi], B0);
                    mma16816(acc[mi][nf], ah[mi], B1);
                    mma16816(acc[mi][nf], al[mi], B0);
                }
        }
    }

    int mrow = bm + wm + (lane >> 2);
    int ncol0 = (lane & 3) * 2;
#pragma unroll
    for (int mi = 0; mi < 2; mi++) {
        int m0 = mrow + mi * 16;
#pragma unroll
        for (int nf = 0; nf < 4; nf++) {
            int n0 = bn + wn + nf * 8 + ncol0;
            float b0 = bias[n0], b1 = bias[n0 + 1];
            float v00 = acc[mi][nf][0] + b0, v01 = acc[mi][nf][1] + b1;
            float v10 = acc[mi][nf][2] + b0, v11 = acc[mi][nf][3] + b1;
            size_t o0 = (size_t)m0 * N + n0;
            size_t o1 = (size_t)(m0 + 8) * N + n0;
            if (EPI == EPI_GELU) {
                split2_store(gelu_tanh(v00), gelu_tanh(v01), Chi, Clo, o0);
                split2_store(gelu_tanh(v10), gelu_tanh(v11), Chi, Clo, o1);
            } else if (EPI == EPI_SPLIT) {
                split2_store(v00, v01, Chi, Clo, o0);
                split2_store(v10, v11, Chi, Clo, o1);
            } else {
                if (EPI == EPI_RES) {
                    float2 r0 = *(const float2*)(res + o0);
                    float2 r1 = *(const float2*)(res + o1);
                    v00 += r0.x; v01 += r0.y; v10 += r1.x; v11 += r1.y;
                }
                float2 s0 = {v00, v01}, s1 = {v10, v11};
                *(float2*)(Cf + o0) = s0;
                *(float2*)(Cf + o1) = s1;
            }
        }
    }
}

// ---------------------------------------------------------------------------
// Flash attention on mma.sync (bf16 split, causal). Unchanged from R9.
// ---------------------------------------------------------------------------
#define AROW 272
#define AT_KH 0
#define AT_KL 17408
#define AT_VH 34816
#define AT_VL 52224
#define AT_STAGE 69632
#define AT_QH (2 * AT_STAGE)
#define AT_QL (AT_QH + 128 * AROW)
#define ATTN_SMEM (AT_QL + 128 * AROW)

__device__ __forceinline__ void attn_load_kv(
    uint32_t st, const __nv_bfloat16* __restrict__ qh, const __nv_bfloat16* __restrict__ ql,
    int bb, int h, int k0, int tid)
{
#pragma unroll
    for (int it = 0; it < 4; it++) {
        int c = tid + it * 256;
        int row = c >> 4, ch = c & 15;
        uint32_t off = (uint32_t)row * AROW + ch * 16;
        size_t g = (size_t)(bb * S_ + k0 + row) * QKV_STRIDE + h * D_ + ch * 8;
        cpa16(st + AT_KH + off, qh + g + E_);
        cpa16(st + AT_KL + off, ql + g + E_);
        cpa16(st + AT_VH + off, qh + g + 2 * E_);
        cpa16(st + AT_VL + off, ql + g + 2 * E_);
    }
    CP_COMMIT();
}

__global__ __launch_bounds__(256, 1) void attn_mma_kernel(
    const __nv_bfloat16* __restrict__ qkvh, const __nv_bfloat16* __restrict__ qkvl,
    __nv_bfloat16* __restrict__ ctx_hi, __nv_bfloat16* __restrict__ ctx_lo)
{
    extern __shared__ char smem[];
    uint32_t sb = smem_to_u32(smem);
    int tid = threadIdx.x;
    int wid = tid >> 5, lane = tid & 31;
    int q0 = blockIdx.x * 128;
    int h = blockIdx.y, bb = blockIdx.z;
    int wbase = wid * 16;

#pragma unroll
    for (int it = 0; it < 8; it++) {
        int c = tid + it * 256;
        int row = c >> 4, ch = c & 15;
        uint32_t off = (uint32_t)row * AROW + ch * 16;
        size_t g = (size_t)(bb * S_ + q0 + row) * QKV_STRIDE + h * D_ + ch * 8;
        cpa16(sb + AT_QH + off, qkvh + g);
        cpa16(sb + AT_QL + off, qkvl + g);
    }
    CP_COMMIT();
    attn_load_kv(sb, qkvh, qkvl, bb, h, 0, tid);

    uint32_t a_off = (uint32_t)(wbase + (lane & 15)) * AROW + ((lane >> 4) * 16);
    uint32_t b_off = (uint32_t)((lane & 7) + ((lane >> 4) * 8)) * AROW + (((lane >> 3) & 1) * 16);
    uint32_t v_off = (uint32_t)(lane & 15) * AROW + ((lane >> 4) * 8) * 2;

    const float SCL = 0.08838834764831845f * 1.4426950408889634f;
    int row_lo = q0 + wbase + (lane >> 2);
    int row_hi = row_lo + 8;

    float o[16][4];
#pragma unroll
    for (int i = 0; i < 16; i++)
#pragma unroll
        for (int j = 0; j < 4; j++) o[i][j] = 0.f;
    float m_lo = -1e30f, m_hi = -1e30f, l_lo = 0.f, l_hi = 0.f;

    int nt = q0 / 64 + 2;
    for (int t = 0; t < nt; t++) {
        uint32_t st = sb + (uint32_t)(t & 1) * AT_STAGE;
        if (t + 1 < nt) {
            attn_load_kv(sb + (uint32_t)((t + 1) & 1) * AT_STAGE, qkvh, qkvl, bb, h,
                         (t + 1) * 64, tid);
            asm volatile("cp.async.wait_group 1;" ::: "memory");
        } else {
            asm volatile("cp.async.wait_group 0;" ::: "memory");
        }
        __syncthreads();

        int k0 = t * 64;
        bool skip = (k0 > q0 + wbase + 15);
        if (!skip) {
            float sacc[8][4];
#pragma unroll
            for (int i = 0; i < 8; i++)
#pragma unroll
                for (int j = 0; j < 4; j++) sacc[i][j] = 0.f;

#pragma unroll
            for (int ks = 0; ks < 8; ks++) {
                uint32_t koff = (uint32_t)ks * 32;
                uint32_t qfh[4], qfl[4];
                ldsm4(qfh[0], qfh[1], qfh[2], qfh[3], sb + AT_QH + a_off + koff);
                ldsm4(qfl[0], qfl[1], qfl[2], qfl[3], sb + AT_QL + a_off + koff);
#pragma unroll
                for (int g = 0; g < 4; g++) {
                    uint32_t kh[4], kl[4];
                    uint32_t rb = st + AT_KH + b_off + (uint32_t)g * (16 * AROW) + koff;
                    ldsm4(kh[0], kh[1], kh[2], kh[3], rb);
                    ldsm4(kl[0], kl[1], kl[2], kl[3], rb + (AT_KL - AT_KH));
                    mma16816(sacc[2 * g],     qfh, &kh[0]);
                    mma16816(sacc[2 * g],     qfh, &kl[0]);
                    mma16816(sacc[2 * g],     qfl, &kh[0]);
                    mma16816(sacc[2 * g + 1], qfh, &kh[2]);
                    mma16816(sacc[2 * g + 1], qfh, &kl[2]);
                    mma16816(sacc[2 * g + 1], qfl, &kh[2]);
                }
            }

            bool needmask = (k0 + 63) > (q0 + wbase);
#pragma unroll
            for (int nf = 0; nf < 8; nf++) {
                int col = k0 + nf * 8 + (lane & 3) * 2;
                float s0 = sacc[nf][0] * SCL, s1 = sacc[nf][1] * SCL;
                float s2 = sacc[nf][2] * SCL, s3 = sacc[nf][3] * SCL;
                if (needmask) {
                    if (col     > row_lo) s0 = -1e30f;
                    if (col + 1 > row_lo) s1 = -1e30f;
                    if (col     > row_hi) s2 = -1e30f;
                    if (col + 1 > row_hi) s3 = -1e30f;
                }
                sacc[nf][0] = s0; sacc[nf][1] = s1; sacc[nf][2] = s2; sacc[nf][3] = s3;
            }

            float mx_lo = -1e30f, mx_hi = -1e30f;
#pragma unroll
            for (int nf = 0; nf < 8; nf++) {
                mx_lo = fmaxf(mx_lo, fmaxf(sacc[nf][0], sacc[nf][1]));
                mx_hi = fmaxf(mx_hi, fmaxf(sacc[nf][2], sacc[nf][3]));
            }
            mx_lo = fmaxf(mx_lo, __shfl_xor_sync(0xffffffffu, mx_lo, 1));
            mx_lo = fmaxf(mx_lo, __shfl_xor_sync(0xffffffffu, mx_lo, 2));
            mx_hi = fmaxf(mx_hi, __shfl_xor_sync(0xffffffffu, mx_hi, 1));
            mx_hi = fmaxf(mx_hi, __shfl_xor_sync(0xffffffffu, mx_hi, 2));

            float mn_lo = fmaxf(m_lo, mx_lo), mn_hi = fmaxf(m_hi, mx_hi);
            float al_lo = exp2f(m_lo - mn_lo), al_hi = exp2f(m_hi - mn_hi);
            m_lo = mn_lo; m_hi = mn_hi;

            float sum_lo = 0.f, sum_hi = 0.f;
#pragma unroll
            for (int nf = 0; nf < 8; nf++) {
                float p0 = exp2f(sacc[nf][0] - m_lo);
                float p1 = exp2f(sacc[nf][1] - m_lo);
                float p2 = exp2f(sacc[nf][2] - m_hi);
                float p3 = exp2f(sacc[nf][3] - m_hi);
                sum_lo += p0 + p1; sum_hi += p2 + p3;
                sacc[nf][0] = p0; sacc[nf][1] = p1; sacc[nf][2] = p2; sacc[nf][3] = p3;
            }
            sum_lo += __shfl_xor_sync(0xffffffffu, sum_lo, 1);
            sum_lo += __shfl_xor_sync(0xffffffffu, sum_lo, 2);
            sum_hi += __shfl_xor_sync(0xffffffffu, sum_hi, 1);
            sum_hi += __shfl_xor_sync(0xffffffffu, sum_hi, 2);
            l_lo = l_lo * al_lo + sum_lo;
            l_hi = l_hi * al_hi + sum_hi;

#pragma unroll
            for (int i = 0; i < 16; i++) {
                o[i][0] *= al_lo; o[i][1] *= al_lo;
                o[i][2] *= al_hi; o[i][3] *= al_hi;
            }

            uint32_t pah[4][4], pal[4][4];
#pragma unroll
            for (int ks = 0; ks < 4; ks++) {
                splitpack(sacc[2 * ks][0],     sacc[2 * ks][1],     pah[ks][0], pal[ks][0]);
                splitpack(sacc[2 * ks][2],     sacc[2 * ks][3],     pah[ks][1], pal[ks][1]);
                splitpack(sacc[2 * ks + 1][0], sacc[2 * ks + 1][1], pah[ks][2], pal[ks][2]);
                splitpack(sacc[2 * ks + 1][2], sacc[2 * ks + 1][3], pah[ks][3], pal[ks][3]);
            }

#pragma unroll
            for (int ks = 0; ks < 4; ks++) {
#pragma unroll
                for (int dg = 0; dg < 8; dg++) {
                    uint32_t vh[4], vl[4];
                    uint32_t rv = st + AT_VH + v_off + (uint32_t)ks * (16 * AROW) + dg * 32;
                    ldsm4t(vh[0], vh[1], vh[2], vh[3], rv);
                    ldsm4t(vl[0], vl[1], vl[2], vl[3], rv + (AT_VL - AT_VH));
                    mma16816(o[2 * dg],     pah[ks], &vh[0]);
                    mma16816(o[2 * dg],     pah[ks], &vl[0]);
                    mma16816(o[2 * dg],     pal[ks], &vh[0]);
                    mma16816(o[2 * dg + 1], pah[ks], &vh[2]);
                    mma16816(o[2 * dg + 1], pah[ks], &vl[2]);
                    mma16816(o[2 * dg + 1], pal[ks], &vh[2]);
                }
            }
        }
        __syncthreads();
    }

    float li_lo = 1.f / l_lo, li_hi = 1.f / l_hi;
    size_t base_lo = (size_t)(bb * S_ + row_lo) * E_ + h * D_;
    size_t base_hi = (size_t)(bb * S_ + row_hi) * E_ + h * D_;
#pragma unroll
    for (int dgf = 0; dgf < 16; dgf++) {
        int col = dgf * 8 + (lane & 3) * 2;
        split2_store(o[dgf][0] * li_lo, o[dgf][1] * li_lo, ctx_hi, ctx_lo, base_lo + col);
        split2_store(o[dgf][2] * li_hi, o[dgf][3] * li_hi, ctx_hi, ctx_lo, base_hi + col);
    }
}

// ---------------------------------------------------------------------------
// Launch
// ---------------------------------------------------------------------------
extern "C" void kernel_launch(void* const* d_in, const int* in_sizes, int n_in,
                              void* d_out, int out_size)
{
    const float* x            = (const float*)d_in[0];
    const float* ln1_w        = (const float*)d_in[1];
    const float* ln1_b        = (const float*)d_in[2];
    const float* c_attn_w     = (const float*)d_in[3];
    const float* c_attn_b     = (const float*)d_in[4];
    const float* c_proj_w     = (const float*)d_in[5];
    const float* c_proj_b     = (const float*)d_in[6];
    const float* ln2_w        = (const float*)d_in[7];
    const float* ln2_b        = (const float*)d_in[8];
    const float* c_fc_w       = (const float*)d_in[9];
    const float* c_fc_b       = (const float*)d_in[10];
    const float* c_mlp_proj_w = (const float*)d_in[11];
    const float* c_mlp_proj_b = (const float*)d_in[12];
    float* out = (float*)d_out;

    void *p_wh, *p_wl, *p_ah, *p_al, *p_fh, *p_fl;
    cudaGetSymbolAddress(&p_wh, g_wt_hi);
    cudaGetSymbolAddress(&p_wl, g_wt_lo);
    cudaGetSymbolAddress(&p_ah, g_act_hi);
    cudaGetSymbolAddress(&p_al, g_act_lo);
    cudaGetSymbolAddress(&p_fh, g_fc_hi);
    cudaGetSymbolAddress(&p_fl, g_fc_lo);
    __nv_bfloat16* wh = (__nv_bfloat16*)p_wh;
    __nv_bfloat16* wl = (__nv_bfloat16*)p_wl;
    __nv_bfloat16* ah = (__nv_bfloat16*)p_ah;
    __nv_bfloat16* al = (__nv_bfloat16*)p_al;
    __nv_bfloat16* fh = (__nv_bfloat16*)p_fh;   // also qkv hi plane
    __nv_bfloat16* fl = (__nv_bfloat16*)p_fl;   // also qkv lo plane

    cudaFuncSetAttribute(attn_mma_kernel, cudaFuncAttributeMaxDynamicSharedMemorySize, ATTN_SMEM);
    cudaFuncSetAttribute(hmma_kernel<EPI_SPLIT>, cudaFuncAttributeMaxDynamicSharedMemorySize, HMMA_SMEM);
    cudaFuncSetAttribute(hmma_kernel<EPI_GELU>,  cudaFuncAttributeMaxDynamicSharedMemorySize, HMMA_SMEM);
    cudaFuncSetAttribute(hmma_kernel<EPI_RES>,   cudaFuncAttributeMaxDynamicSharedMemorySize, HMMA_SMEM);

    dim3 tb(32, 8);
    wsplit_t_kernel<<<dim3(6144 / 32, 2048 / 32), tb>>>(c_attn_w,     wh + WOFF_QKV,  wl + WOFF_QKV,  2048, 6144);
    wsplit_t_kernel<<<dim3(2048 / 32, 2048 / 32), tb>>>(c_proj_w,     wh + WOFF_PROJ, wl + WOFF_PROJ, 2048, 2048);
    wsplit_t_kernel<<<dim3(8192 / 32, 2048 / 32), tb>>>(c_fc_w,       wh + WOFF_FC,   wl + WOFF_FC,   2048, 8192);
    wsplit_t_kernel<<<dim3(2048 / 32, 8192 / 32), tb>>>(c_mlp_proj_w, wh + WOFF_MLP,  wl + WOFF_MLP,  8192, 2048);

    // 1. ln1(x) -> act planes
    ln_kernel<<<NTOK, 256>>>(x, ln1_w, ln1_b, ah, al);

    // 2. qkv = ln1 @ Wqkv + b -> bf16 hi/lo planes (aliased into fc buffers)
    hmma_kernel<EPI_SPLIT><<<dim3(QKV_STRIDE / BN, NTOK / BM), 512, HMMA_SMEM>>>(
        ah, al, wh + WOFF_QKV, wl + WOFF_QKV, c_attn_b, nullptr,
        nullptr, fh, fl, NTOK, QKV_STRIDE, E_);

    // 3. attention (tensor-core) -> ctx planes
    attn_mma_kernel<<<dim3(S_ / 128, H_, B_), 256, ATTN_SMEM>>>(fh, fl, ah, al);

    // 4. x2 = ctx @ Wproj + b + x -> d_out (fp32)
    hmma_kernel<EPI_RES><<<dim3(E_ / BN, NTOK / BM), 512, HMMA_SMEM>>>(
        ah, al, wh + WOFF_PROJ, wl + WOFF_PROJ, c_proj_b, x,
        out, nullptr, nullptr, NTOK, E_, E_);

    // 5. ln2(x2) -> act planes
    ln_kernel<<<NTOK, 256>>>(out, ln2_w, ln2_b, ah, al);

    // 6. fc = gelu(ln2 @ Wfc + b) -> fc planes (overwrites qkv planes; safe)
    hmma_kernel<EPI_GELU><<<dim3(F_ / BN, NTOK / BM), 512, HMMA_SMEM>>>(
        ah, al, wh + WOFF_FC, wl + WOFF_FC, c_fc_b, nullptr,
        nullptr, fh, fl, NTOK, F_, E_);

    // 7. out = fc @ Wmlp + b + x2 -> d_out (fp32, in-place residual)
    hmma_kernel<EPI_RES><<<dim3(E_ / BN, NTOK / BM), 512, HMMA_SMEM>>>(
        fh, fl, wh + WOFF_MLP, wl + WOFF_MLP, c_mlp_proj_b, out,
        out, nullptr, nullptr, NTOK, E_, F_);

    (void)in_sizes; (void)n_in; (void)out_size;
}

// round 12
// speedup vs baseline: 1.0237x; 1.0237x over previous
#include <cuda_runtime.h>
#include <cuda_bf16.h>
#include <math.h>
#include <stdint.h>

// Problem dims (fixed)
#define B_  4
#define S_  2048
#define E_  2048
#define H_  16
#define D_  128
#define F_  8192
#define NTOK (B_ * S_)
#define QKV_STRIDE (3 * E_)

// ---------------------------------------------------------------------------
// Scratch (device globals)
// ---------------------------------------------------------------------------
#define WOFF_QKV 0u
#define WOFF_PROJ 12582912u               // 6144*2048
#define WOFF_FC   16777216u               // + 2048*2048
#define WOFF_MLP  33554432u               // + 2048*8192
#define WTOT      50331648u               // + 8192*2048
__device__ __nv_bfloat16 g_wt_hi[WTOT];
__device__ __nv_bfloat16 g_wt_lo[WTOT];
__device__ __nv_bfloat16 g_act_hi[(size_t)NTOK * E_];
__device__ __nv_bfloat16 g_act_lo[(size_t)NTOK * E_];
__device__ __nv_bfloat16 g_fc_hi[(size_t)NTOK * F_];   // also qkv hi plane
__device__ __nv_bfloat16 g_fc_lo[(size_t)NTOK * F_];   // also qkv lo plane

// ---------------------------------------------------------------------------
// PTX helpers (portable sm_80+ subset only)
// ---------------------------------------------------------------------------
__device__ __forceinline__ uint32_t smem_to_u32(const void* p) {
    uint32_t a;
    asm("{ .reg .u64 t; cvta.to.shared.u64 t, %1; cvt.u32.u64 %0, t; }" : "=r"(a) : "l"(p));
    return a;
}
__device__ __forceinline__ void cpa16(uint32_t dst, const void* src) {
    asm volatile("cp.async.cg.shared.global [%0], [%1], 16;" :: "r"(dst), "l"(src) : "memory");
}
#define CP_COMMIT() asm volatile("cp.async.commit_group;" ::: "memory")

__device__ __forceinline__ void ldsm4(uint32_t& r0, uint32_t& r1, uint32_t& r2, uint32_t& r3,
                                      uint32_t a) {
    asm volatile("ldmatrix.sync.aligned.m8n8.x4.shared.b16 {%0,%1,%2,%3}, [%4];"
                 : "=r"(r0), "=r"(r1), "=r"(r2), "=r"(r3) : "r"(a));
}
__device__ __forceinline__ void ldsm4t(uint32_t& r0, uint32_t& r1, uint32_t& r2, uint32_t& r3,
                                       uint32_t a) {
    asm volatile("ldmatrix.sync.aligned.m8n8.x4.trans.shared.b16 {%0,%1,%2,%3}, [%4];"
                 : "=r"(r0), "=r"(r1), "=r"(r2), "=r"(r3) : "r"(a));
}
__device__ __forceinline__ void mma16816(float* c, const uint32_t* a, const uint32_t* b) {
    asm volatile(
        "mma.sync.aligned.m16n8k16.row.col.f32.bf16.bf16.f32 "
        "{%0,%1,%2,%3}, {%4,%5,%6,%7}, {%8,%9}, {%0,%1,%2,%3};"
        : "+f"(c[0]), "+f"(c[1]), "+f"(c[2]), "+f"(c[3])
        : "r"(a[0]), "r"(a[1]), "r"(a[2]), "r"(a[3]), "r"(b[0]), "r"(b[1]));
}

__device__ __forceinline__ void split2_store(float a, float b,
                                             __nv_bfloat16* hp, __nv_bfloat16* lp, size_t idx) {
    __nv_bfloat16 ha = __float2bfloat16(a);
    __nv_bfloat16 hb = __float2bfloat16(b);
    __nv_bfloat16 la = __float2bfloat16(a - __bfloat162float(ha));
    __nv_bfloat16 lb = __float2bfloat16(b - __bfloat162float(hb));
    __nv_bfloat162 h2; h2.x = ha; h2.y = hb;
    __nv_bfloat162 l2; l2.x = la; l2.y = lb;
    *(__nv_bfloat162*)(hp + idx) = h2;
    *(__nv_bfloat162*)(lp + idx) = l2;
}
__device__ __forceinline__ void splitpack(float a, float b, uint32_t& hi, uint32_t& lo) {
    __nv_bfloat16 ha = __float2bfloat16(a);
    __nv_bfloat16 hb = __float2bfloat16(b);
    __nv_bfloat16 la = __float2bfloat16(a - __bfloat162float(ha));
    __nv_bfloat16 lb = __float2bfloat16(b - __bfloat162float(hb));
    hi = (uint32_t)__bfloat16_as_ushort(ha) | ((uint32_t)__bfloat16_as_ushort(hb) << 16);
    lo = (uint32_t)__bfloat16_as_ushort(la) | ((uint32_t)__bfloat16_as_ushort(lb) << 16);
}

// ---------------------------------------------------------------------------
// Weight prep: W[K,N] fp32 -> Th/Tl[N,K] bf16 (transpose + split)
// ---------------------------------------------------------------------------
__global__ __launch_bounds__(256) void wsplit_t_kernel(
    const float* __restrict__ W, __nv_bfloat16* __restrict__ Th,
    __nv_bfloat16* __restrict__ Tl, int K, int N)
{
    __shared__ float s[32][33];
    int n0 = blockIdx.x * 32, k0 = blockIdx.y * 32;
    int tx = threadIdx.x, ty = threadIdx.y;
#pragma unroll
    for (int j = 0; j < 4; j++)
        s[ty + j * 8][tx] = W[(size_t)(k0 + ty + j * 8) * N + n0 + tx];
    __syncthreads();
#pragma unroll
    for (int j = 0; j < 4; j++) {
        float v = s[tx][ty + j * 8];
        __nv_bfloat16 h = __float2bfloat16(v);
        __nv_bfloat16 l = __float2bfloat16(v - __bfloat162float(h));
        size_t o = (size_t)(n0 + ty + j * 8) * K + k0 + tx;
        Th[o] = h; Tl[o] = l;
    }
}

// ---------------------------------------------------------------------------
// Block reduction (256 threads)
// ---------------------------------------------------------------------------
__device__ __forceinline__ float blk_reduce_sum(float v, float* sbuf) {
    int lane = threadIdx.x & 31, wid = threadIdx.x >> 5;
#pragma unroll
    for (int o = 16; o; o >>= 1) v += __shfl_xor_sync(0xffffffffu, v, o);
    if (lane == 0) sbuf[wid] = v;
    __syncthreads();
    if (threadIdx.x < 32) {
        float u = (threadIdx.x < 8) ? sbuf[threadIdx.x] : 0.f;
#pragma unroll
        for (int o = 4; o; o >>= 1) u += __shfl_xor_sync(0xffffffffu, u, o);
        if (threadIdx.x == 0) sbuf[0] = u;
    }
    __syncthreads();
    float r = sbuf[0];
    __syncthreads();
    return r;
}

// ---------------------------------------------------------------------------
// LayerNorm -> bf16 hi/lo planes
// ---------------------------------------------------------------------------
__global__ __launch_bounds__(256) void ln_kernel(
    const float* __restrict__ x, const float* __restrict__ w,
    const float* __restrict__ b, __nv_bfloat16* __restrict__ oh,
    __nv_bfloat16* __restrict__ ol)
{
    __shared__ float sbuf[8];
    size_t base = (size_t)blockIdx.x * E_;
    int t = threadIdx.x;

    float4 v0 = *(const float4*)(x + base + 4 * t);
    float4 v1 = *(const float4*)(x + base + 4 * t + 1024);
    float s = v0.x + v0.y + v0.z + v0.w + v1.x + v1.y + v1.z + v1.w;
    float mean = blk_reduce_sum(s, sbuf) * (1.f / E_);
    float d, sq = 0.f;
    d = v0.x - mean; sq += d * d;  d = v0.y - mean; sq += d * d;
    d = v0.z - mean; sq += d * d;  d = v0.w - mean; sq += d * d;
    d = v1.x - mean; sq += d * d;  d = v1.y - mean; sq += d * d;
    d = v1.z - mean; sq += d * d;  d = v1.w - mean; sq += d * d;
    float var = blk_reduce_sum(sq, sbuf) * (1.f / E_);
    float r = rsqrtf(var + 1e-5f);

    float4 w0 = *(const float4*)(w + 4 * t);
    float4 w1 = *(const float4*)(w + 4 * t + 1024);
    float4 b0 = *(const float4*)(b + 4 * t);
    float4 b1 = *(const float4*)(b + 4 * t + 1024);

    float o0x = (v0.x - mean) * r * w0.x + b0.x;
    float o0y = (v0.y - mean) * r * w0.y + b0.y;
    float o0z = (v0.z - mean) * r * w0.z + b0.z;
    float o0w = (v0.w - mean) * r * w0.w + b0.w;
    float o1x = (v1.x - mean) * r * w1.x + b1.x;
    float o1y = (v1.y - mean) * r * w1.y + b1.y;
    float o1z = (v1.z - mean) * r * w1.z + b1.z;
    float o1w = (v1.w - mean) * r * w1.w + b1.w;

    split2_store(o0x, o0y, oh, ol, base + 4 * t);
    split2_store(o0z, o0w, oh, ol, base + 4 * t + 2);
    split2_store(o1x, o1y, oh, ol, base + 4 * t + 1024);
    split2_store(o1z, o1w, oh, ol, base + 4 * t + 1026);
}

// ---------------------------------------------------------------------------
// HMMA GEMM: CTA 128x256, 8 warps (2m x 4n), warp tile 64x64, 256 threads,
// BK=32, 3-stage cp.async pipeline. 3-term bf16 split.
// smem traffic: 85 B per HMMA (was 128) — relieves smem-BW co-bound.
// ---------------------------------------------------------------------------
#define EPI_QKV   0
#define EPI_GELU  1
#define EPI_RES   2
#define EPI_SPLIT 3

#define BM 128
#define BN 256
#define BK 32
#define ROWB 80
#define SA_H 0
#define SA_L 10240
#define SB_H 20480
#define SB_L 40960
#define STAGE_BYTES 61440
#define HMMA_SMEM (3 * STAGE_BYTES)   // 184320

__device__ __forceinline__ float gelu_tanh(float x) {
    float x3 = x * x * x;
    float t = tanhf(0.7978845608028654f * (x + 0.044715f * x3));
    return 0.5f * x * (1.f + t);
}

__device__ __forceinline__ void g2s_stage(
    uint32_t sb, const __nv_bfloat16* __restrict__ Ah, const __nv_bfloat16* __restrict__ Al,
    const __nv_bfloat16* __restrict__ Bh, const __nv_bfloat16* __restrict__ Bl,
    int bm, int bn, int K, int k0, int tid)
{
    // A: 128 rows x 4 chunks = 512 chunks per plane (2 iters of 256 thr)
#pragma unroll
    for (int it = 0; it < 2; it++) {
        int c = tid + it * 256;
        int row = c >> 2, ch = c & 3;
        uint32_t off = (uint32_t)row * ROWB + ch * 16;
        size_t ga = (size_t)(bm + row) * K + k0 + ch * 8;
        cpa16(sb + SA_H + off, Ah + ga);
        cpa16(sb + SA_L + off, Al + ga);
    }
    // B: 256 rows x 4 chunks = 1024 chunks per plane (4 iters)
#pragma unroll
    for (int it = 0; it < 4; it++) {
        int c = tid + it * 256;
        int row = c >> 2, ch = c & 3;
        uint32_t off = (uint32_t)row * ROWB + ch * 16;
        size_t gb = (size_t)(bn + row) * K + k0 + ch * 8;
        cpa16(sb + SB_H + off, Bh + gb);
        cpa16(sb + SB_L + off, Bl + gb);
    }
    CP_COMMIT();
}

template <int EPI>
__global__ __launch_bounds__(256, 1) void hmma_kernel(
    const __nv_bfloat16* __restrict__ Ah, const __nv_bfloat16* __restrict__ Al,
    const __nv_bfloat16* __restrict__ Bh, const __nv_bfloat16* __restrict__ Bl,
    const float* __restrict__ bias, const float* __restrict__ res,
    float* __restrict__ Cf, __nv_bfloat16* __restrict__ Chi,
    __nv_bfloat16* __restrict__ Clo, int M, int N, int K)
{
    extern __shared__ char smem[];
    uint32_t sb0 = smem_to_u32(smem);
    int tid = threadIdx.x;
    int wid = tid >> 5, lane = tid & 31;
    int wm = (wid & 1) * 64, wn = (wid >> 1) * 64;
    int bm = blockIdx.y * BM, bn = blockIdx.x * BN;

    float acc[4][8][4];
#pragma unroll
    for (int i = 0; i < 4; i++)
#pragma unroll
        for (int j = 0; j < 8; j++)
#pragma unroll
            for (int k = 0; k < 4; k++) acc[i][j][k] = 0.f;

    uint32_t a_off = (uint32_t)(wm + (lane & 15)) * ROWB + ((lane >> 4) * 16);
    uint32_t b_off = (uint32_t)(wn + (lane & 7) + ((lane >> 4) * 8)) * ROWB
                   + (((lane >> 3) & 1) * 16);

    g2s_stage(sb0,               Ah, Al, Bh, Bl, bm, bn, K, 0,  tid);
    g2s_stage(sb0 + STAGE_BYTES, Ah, Al, Bh, Bl, bm, bn, K, BK, tid);

    int nk = K / BK;
    for (int kt = 0; kt < nk; kt++) {
        asm volatile("cp.async.wait_group 1;" ::: "memory");
        __syncthreads();
        if (kt + 2 < nk)
            g2s_stage(sb0 + (uint32_t)((kt + 2) % 3) * STAGE_BYTES,
                      Ah, Al, Bh, Bl, bm, bn, K, (kt + 2) * BK, tid);
        else
            CP_COMMIT();

        uint32_t st = sb0 + (uint32_t)(kt % 3) * STAGE_BYTES;
#pragma unroll
        for (int ks = 0; ks < 2; ks++) {
            uint32_t koff = (uint32_t)ks * 32;
            // Load all A fragments for this k16 slice (4 m-frags x hi/lo)
            uint32_t ah[4][4], al[4][4];
#pragma unroll
            for (int mi = 0; mi < 4; mi++) {
                uint32_t ra = st + SA_H + a_off + (uint32_t)mi * (16 * ROWB) + koff;
                ldsm4(ah[mi][0], ah[mi][1], ah[mi][2], ah[mi][3], ra);
                ldsm4(al[mi][0], al[mi][1], al[mi][2], al[mi][3], ra + (SA_L - SA_H));
            }
            // Stream B n-groups (4 groups of 16 cols), reuse across all mi
#pragma unroll
            for (int ng = 0; ng < 4; ng++) {
                uint32_t bh[4], bl[4];
                uint32_t rb = st + SB_H + b_off + (uint32_t)ng * (16 * ROWB) + koff;
                ldsm4(bh[0], bh[1], bh[2], bh[3], rb);
                ldsm4(bl[0], bl[1], bl[2], bl[3], rb + (SB_L - SB_H));
#pragma unroll
                for (int mi = 0; mi < 4; mi++) {
#pragma unroll
                    for (int sub = 0; sub < 2; sub++) {
                        float* C = acc[mi][2 * ng + sub];
                        mma16816(C, ah[mi], &bh[sub * 2]);
                        mma16816(C, ah[mi], &bl[sub * 2]);
                        mma16816(C, al[mi], &bh[sub * 2]);
                    }
                }
            }
        }
    }

    int mrow = bm + wm + (lane >> 2);
    int ncol0 = (lane & 3) * 2;
#pragma unroll
    for (int mi = 0; mi < 4; mi++) {
        int m0 = mrow + mi * 16;
#pragma unroll
        for (int nf = 0; nf < 8; nf++) {
            int n0 = bn + wn + nf * 8 + ncol0;
            float b0 = bias[n0], b1 = bias[n0 + 1];
            float v00 = acc[mi][nf][0] + b0, v01 = acc[mi][nf][1] + b1;
            float v10 = acc[mi][nf][2] + b0, v11 = acc[mi][nf][3] + b1;
            size_t o0 = (size_t)m0 * N + n0;
            size_t o1 = (size_t)(m0 + 8) * N + n0;
            if (EPI == EPI_GELU) {
                split2_store(gelu_tanh(v00), gelu_tanh(v01), Chi, Clo, o0);
                split2_store(gelu_tanh(v10), gelu_tanh(v11), Chi, Clo, o1);
            } else if (EPI == EPI_SPLIT) {
                split2_store(v00, v01, Chi, Clo, o0);
                split2_store(v10, v11, Chi, Clo, o1);
            } else {
                if (EPI == EPI_RES) {
                    float2 r0 = *(const float2*)(res + o0);
                    float2 r1 = *(const float2*)(res + o1);
                    v00 += r0.x; v01 += r0.y; v10 += r1.x; v11 += r1.y;
                }
                float2 s0 = {v00, v01}, s1 = {v10, v11};
                *(float2*)(Cf + o0) = s0;
                *(float2*)(Cf + o1) = s1;
            }
        }
    }
}

// ---------------------------------------------------------------------------
// Flash attention on mma.sync (bf16 split, causal). Unchanged from R9.
// ---------------------------------------------------------------------------
#define AROW 272
#define AT_KH 0
#define AT_KL 17408
#define AT_VH 34816
#define AT_VL 52224
#define AT_STAGE 69632
#define AT_QH (2 * AT_STAGE)
#define AT_QL (AT_QH + 128 * AROW)
#define ATTN_SMEM (AT_QL + 128 * AROW)

__device__ __forceinline__ void attn_load_kv(
    uint32_t st, const __nv_bfloat16* __restrict__ qh, const __nv_bfloat16* __restrict__ ql,
    int bb, int h, int k0, int tid)
{
#pragma unroll
    for (int it = 0; it < 4; it++) {
        int c = tid + it * 256;
        int row = c >> 4, ch = c & 15;
        uint32_t off = (uint32_t)row * AROW + ch * 16;
        size_t g = (size_t)(bb * S_ + k0 + row) * QKV_STRIDE + h * D_ + ch * 8;
        cpa16(st + AT_KH + off, qh + g + E_);
        cpa16(st + AT_KL + off, ql + g + E_);
        cpa16(st + AT_VH + off, qh + g + 2 * E_);
        cpa16(st + AT_VL + off, ql + g + 2 * E_);
    }
    CP_COMMIT();
}

__global__ __launch_bounds__(256, 1) void attn_mma_kernel(
    const __nv_bfloat16* __restrict__ qkvh, const __nv_bfloat16* __restrict__ qkvl,
    __nv_bfloat16* __restrict__ ctx_hi, __nv_bfloat16* __restrict__ ctx_lo)
{
    extern __shared__ char smem[];
    uint32_t sb = smem_to_u32(smem);
    int tid = threadIdx.x;
    int wid = tid >> 5, lane = tid & 31;
    int q0 = blockIdx.x * 128;
    int h = blockIdx.y, bb = blockIdx.z;
    int wbase = wid * 16;

#pragma unroll
    for (int it = 0; it < 8; it++) {
        int c = tid + it * 256;
        int row = c >> 4, ch = c & 15;
        uint32_t off = (uint32_t)row * AROW + ch * 16;
        size_t g = (size_t)(bb * S_ + q0 + row) * QKV_STRIDE + h * D_ + ch * 8;
        cpa16(sb + AT_QH + off, qkvh + g);
        cpa16(sb + AT_QL + off, qkvl + g);
    }
    CP_COMMIT();
    attn_load_kv(sb, qkvh, qkvl, bb, h, 0, tid);

    uint32_t a_off = (uint32_t)(wbase + (lane & 15)) * AROW + ((lane >> 4) * 16);
    uint32_t b_off = (uint32_t)((lane & 7) + ((lane >> 4) * 8)) * AROW + (((lane >> 3) & 1) * 16);
    uint32_t v_off = (uint32_t)(lane & 15) * AROW + ((lane >> 4) * 8) * 2;

    const float SCL = 0.08838834764831845f * 1.4426950408889634f;
    int row_lo = q0 + wbase + (lane >> 2);
    int row_hi = row_lo + 8;

    float o[16][4];
#pragma unroll
    for (int i = 0; i < 16; i++)
#pragma unroll
        for (int j = 0; j < 4; j++) o[i][j] = 0.f;
    float m_lo = -1e30f, m_hi = -1e30f, l_lo = 0.f, l_hi = 0.f;

    int nt = q0 / 64 + 2;
    for (int t = 0; t < nt; t++) {
        uint32_t st = sb + (uint32_t)(t & 1) * AT_STAGE;
        if (t + 1 < nt) {
            attn_load_kv(sb + (uint32_t)((t + 1) & 1) * AT_STAGE, qkvh, qkvl, bb, h,
                         (t + 1) * 64, tid);
            asm volatile("cp.async.wait_group 1;" ::: "memory");
        } else {
            asm volatile("cp.async.wait_group 0;" ::: "memory");
        }
        __syncthreads();

        int k0 = t * 64;
        bool skip = (k0 > q0 + wbase + 15);
        if (!skip) {
            float sacc[8][4];
#pragma unroll
            for (int i = 0; i < 8; i++)
#pragma unroll
                for (int j = 0; j < 4; j++) sacc[i][j] = 0.f;

#pragma unroll
            for (int ks = 0; ks < 8; ks++) {
                uint32_t koff = (uint32_t)ks * 32;
                uint32_t qfh[4], qfl[4];
                ldsm4(qfh[0], qfh[1], qfh[2], qfh[3], sb + AT_QH + a_off + koff);
                ldsm4(qfl[0], qfl[1], qfl[2], qfl[3], sb + AT_QL + a_off + koff);
#pragma unroll
                for (int g = 0; g < 4; g++) {
                    uint32_t kh[4], kl[4];
                    uint32_t rb = st + AT_KH + b_off + (uint32_t)g * (16 * AROW) + koff;
                    ldsm4(kh[0], kh[1], kh[2], kh[3], rb);
                    ldsm4(kl[0], kl[1], kl[2], kl[3], rb + (AT_KL - AT_KH));
                    mma16816(sacc[2 * g],     qfh, &kh[0]);
                    mma16816(sacc[2 * g],     qfh, &kl[0]);
                    mma16816(sacc[2 * g],     qfl, &kh[0]);
                    mma16816(sacc[2 * g + 1], qfh, &kh[2]);
                    mma16816(sacc[2 * g + 1], qfh, &kl[2]);
                    mma16816(sacc[2 * g + 1], qfl, &kh[2]);
                }
            }

            bool needmask = (k0 + 63) > (q0 + wbase);
#pragma unroll
            for (int nf = 0; nf < 8; nf++) {
                int col = k0 + nf * 8 + (lane & 3) * 2;
                float s0 = sacc[nf][0] * SCL, s1 = sacc[nf][1] * SCL;
                float s2 = sacc[nf][2] * SCL, s3 = sacc[nf][3] * SCL;
                if (needmask) {
                    if (col     > row_lo) s0 = -1e30f;
                    if (col + 1 > row_lo) s1 = -1e30f;
                    if (col     > row_hi) s2 = -1e30f;
                    if (col + 1 > row_hi) s3 = -1e30f;
                }
                sacc[nf][0] = s0; sacc[nf][1] = s1; sacc[nf][2] = s2; sacc[nf][3] = s3;
            }

            float mx_lo = -1e30f, mx_hi = -1e30f;
#pragma unroll
            for (int nf = 0; nf < 8; nf++) {
                mx_lo = fmaxf(mx_lo, fmaxf(sacc[nf][0], sacc[nf][1]));
                mx_hi = fmaxf(mx_hi, fmaxf(sacc[nf][2], sacc[nf][3]));
            }
            mx_lo = fmaxf(mx_lo, __shfl_xor_sync(0xffffffffu, mx_lo, 1));
            mx_lo = fmaxf(mx_lo, __shfl_xor_sync(0xffffffffu, mx_lo, 2));
            mx_hi = fmaxf(mx_hi, __shfl_xor_sync(0xffffffffu, mx_hi, 1));
            mx_hi = fmaxf(mx_hi, __shfl_xor_sync(0xffffffffu, mx_hi, 2));

            float mn_lo = fmaxf(m_lo, mx_lo), mn_hi = fmaxf(m_hi, mx_hi);
            float al_lo = exp2f(m_lo - mn_lo), al_hi = exp2f(m_hi - mn_hi);
            m_lo = mn_lo; m_hi = mn_hi;

            float sum_lo = 0.f, sum_hi = 0.f;
#pragma unroll
            for (int nf = 0; nf < 8; nf++) {
                float p0 = exp2f(sacc[nf][0] - m_lo);
                float p1 = exp2f(sacc[nf][1] - m_lo);
                float p2 = exp2f(sacc[nf][2] - m_hi);
                float p3 = exp2f(sacc[nf][3] - m_hi);
                sum_lo += p0 + p1; sum_hi += p2 + p3;
                sacc[nf][0] = p0; sacc[nf][1] = p1; sacc[nf][2] = p2; sacc[nf][3] = p3;
            }
            sum_lo += __shfl_xor_sync(0xffffffffu, sum_lo, 1);
            sum_lo += __shfl_xor_sync(0xffffffffu, sum_lo, 2);
            sum_hi += __shfl_xor_sync(0xffffffffu, sum_hi, 1);
            sum_hi += __shfl_xor_sync(0xffffffffu, sum_hi, 2);
            l_lo = l_lo * al_lo + sum_lo;
            l_hi = l_hi * al_hi + sum_hi;

#pragma unroll
            for (int i = 0; i < 16; i++) {
                o[i][0] *= al_lo; o[i][1] *= al_lo;
                o[i][2] *= al_hi; o[i][3] *= al_hi;
            }

            uint32_t pah[4][4], pal[4][4];
#pragma unroll
            for (int ks = 0; ks < 4; ks++) {
                splitpack(sacc[2 * ks][0],     sacc[2 * ks][1],     pah[ks][0], pal[ks][0]);
                splitpack(sacc[2 * ks][2],     sacc[2 * ks][3],     pah[ks][1], pal[ks][1]);
                splitpack(sacc[2 * ks + 1][0], sacc[2 * ks + 1][1], pah[ks][2], pal[ks][2]);
                splitpack(sacc[2 * ks + 1][2], sacc[2 * ks + 1][3], pah[ks][3], pal[ks][3]);
            }

#pragma unroll
            for (int ks = 0; ks < 4; ks++) {
#pragma unroll
                for (int dg = 0; dg < 8; dg++) {
                    uint32_t vh[4], vl[4];
                    uint32_t rv = st + AT_VH + v_off + (uint32_t)ks * (16 * AROW) + dg * 32;
                    ldsm4t(vh[0], vh[1], vh[2], vh[3], rv);
                    ldsm4t(vl[0], vl[1], vl[2], vl[3], rv + (AT_VL - AT_VH));
                    mma16816(o[2 * dg],     pah[ks], &vh[0]);
                    mma16816(o[2 * dg],     pah[ks], &vl[0]);
                    mma16816(o[2 * dg],     pal[ks], &vh[0]);
                    mma16816(o[2 * dg + 1], pah[ks], &vh[2]);
                    mma16816(o[2 * dg + 1], pah[ks], &vl[2]);
                    mma16816(o[2 * dg + 1], pal[ks], &vh[2]);
                }
            }
        }
        __syncthreads();
    }

    float li_lo = 1.f / l_lo, li_hi = 1.f / l_hi;
    size_t base_lo = (size_t)(bb * S_ + row_lo) * E_ + h * D_;
    size_t base_hi = (size_t)(bb * S_ + row_hi) * E_ + h * D_;
#pragma unroll
    for (int dgf = 0; dgf < 16; dgf++) {
        int col = dgf * 8 + (lane & 3) * 2;
        split2_store(o[dgf][0] * li_lo, o[dgf][1] * li_lo, ctx_hi, ctx_lo, base_lo + col);
        split2_store(o[dgf][2] * li_hi, o[dgf][3] * li_hi, ctx_hi, ctx_lo, base_hi + col);
    }
}

// ---------------------------------------------------------------------------
// Launch
// ---------------------------------------------------------------------------
extern "C" void kernel_launch(void* const* d_in, const int* in_sizes, int n_in,
                              void* d_out, int out_size)
{
    const float* x            = (const float*)d_in[0];
    const float* ln1_w        = (const float*)d_in[1];
    const float* ln1_b        = (const float*)d_in[2];
    const float* c_attn_w     = (const float*)d_in[3];
    const float* c_attn_b     = (const float*)d_in[4];
    const float* c_proj_w     = (const float*)d_in[5];
    const float* c_proj_b     = (const float*)d_in[6];
    const float* ln2_w        = (const float*)d_in[7];
    const float* ln2_b        = (const float*)d_in[8];
    const float* c_fc_w       = (const float*)d_in[9];
    const float* c_fc_b       = (const float*)d_in[10];
    const float* c_mlp_proj_w = (const float*)d_in[11];
    const float* c_mlp_proj_b = (const float*)d_in[12];
    float* out = (float*)d_out;

    void *p_wh, *p_wl, *p_ah, *p_al, *p_fh, *p_fl;
    cudaGetSymbolAddress(&p_wh, g_wt_hi);
    cudaGetSymbolAddress(&p_wl, g_wt_lo);
    cudaGetSymbolAddress(&p_ah, g_act_hi);
    cudaGetSymbolAddress(&p_al, g_act_lo);
    cudaGetSymbolAddress(&p_fh, g_fc_hi);
    cudaGetSymbolAddress(&p_fl, g_fc_lo);
    __nv_bfloat16* wh = (__nv_bfloat16*)p_wh;
    __nv_bfloat16* wl = (__nv_bfloat16*)p_wl;
    __nv_bfloat16* ah = (__nv_bfloat16*)p_ah;
    __nv_bfloat16* al = (__nv_bfloat16*)p_al;
    __nv_bfloat16* fh = (__nv_bfloat16*)p_fh;   // also qkv hi plane
    __nv_bfloat16* fl = (__nv_bfloat16*)p_fl;   // also qkv lo plane

    cudaFuncSetAttribute(attn_mma_kernel, cudaFuncAttributeMaxDynamicSharedMemorySize, ATTN_SMEM);
    cudaFuncSetAttribute(hmma_kernel<EPI_SPLIT>, cudaFuncAttributeMaxDynamicSharedMemorySize, HMMA_SMEM);
    cudaFuncSetAttribute(hmma_kernel<EPI_GELU>,  cudaFuncAttributeMaxDynamicSharedMemorySize, HMMA_SMEM);
    cudaFuncSetAttribute(hmma_kernel<EPI_RES>,   cudaFuncAttributeMaxDynamicSharedMemorySize, HMMA_SMEM);

    dim3 tb(32, 8);
    wsplit_t_kernel<<<dim3(6144 / 32, 2048 / 32), tb>>>(c_attn_w,     wh + WOFF_QKV,  wl + WOFF_QKV,  2048, 6144);
    wsplit_t_kernel<<<dim3(2048 / 32, 2048 / 32), tb>>>(c_proj_w,     wh + WOFF_PROJ, wl + WOFF_PROJ, 2048, 2048);
    wsplit_t_kernel<<<dim3(8192 / 32, 2048 / 32), tb>>>(c_fc_w,       wh + WOFF_FC,   wl + WOFF_FC,   2048, 8192);
    wsplit_t_kernel<<<dim3(2048 / 32, 8192 / 32), tb>>>(c_mlp_proj_w, wh + WOFF_MLP,  wl + WOFF_MLP,  8192, 2048);

    // 1. ln1(x) -> act planes
    ln_kernel<<<NTOK, 256>>>(x, ln1_w, ln1_b, ah, al);

    // 2. qkv = ln1 @ Wqkv + b -> bf16 hi/lo planes (aliased into fc buffers)
    hmma_kernel<EPI_SPLIT><<<dim3(QKV_STRIDE / BN, NTOK / BM), 256, HMMA_SMEM>>>(
        ah, al, wh + WOFF_QKV, wl + WOFF_QKV, c_attn_b, nullptr,
        nullptr, fh, fl, NTOK, QKV_STRIDE, E_);

    // 3. attention (tensor-core) -> ctx planes
    attn_mma_kernel<<<dim3(S_ / 128, H_, B_), 256, ATTN_SMEM>>>(fh, fl, ah, al);

    // 4. x2 = ctx @ Wproj + b + x -> d_out (fp32)
    hmma_kernel<EPI_RES><<<dim3(E_ / BN, NTOK / BM), 256, HMMA_SMEM>>>(
        ah, al, wh + WOFF_PROJ, wl + WOFF_PROJ, c_proj_b, x,
        out, nullptr, nullptr, NTOK, E_, E_);

    // 5. ln2(x2) -> act planes
    ln_kernel<<<NTOK, 256>>>(out, ln2_w, ln2_b, ah, al);

    // 6. fc = gelu(ln2 @ Wfc + b) -> fc planes (overwrites qkv planes; safe)
    hmma_kernel<EPI_GELU><<<dim3(F_ / BN, NTOK / BM), 256, HMMA_SMEM>>>(
        ah, al, wh + WOFF_FC, wl + WOFF_FC, c_fc_b, nullptr,
        nullptr, fh, fl, NTOK, F_, E_);

    // 7. out = fc @ Wmlp + b + x2 -> d_out (fp32, in-place residual)
    hmma_kernel<EPI_RES><<<dim3(E_ / BN, NTOK / BM), 256, HMMA_SMEM>>>(
        fh, fl, wh + WOFF_MLP, wl + WOFF_MLP, c_mlp_proj_b, out,
        out, nullptr, nullptr, NTOK, E_, F_);

    (void)in_sizes; (void)n_in; (void)out_size;
}

// round 13
// speedup vs baseline: 1.4562x; 1.4225x over previous
#include <cuda_runtime.h>
#include <cuda_fp16.h>
#include <math.h>
#include <stdint.h>

// Problem dims (fixed)
#define B_  4
#define S_  2048
#define E_  2048
#define H_  16
#define D_  128
#define F_  8192
#define NTOK (B_ * S_)
#define QKV_STRIDE (3 * E_)

// ---------------------------------------------------------------------------
// Scratch (device globals)
// ---------------------------------------------------------------------------
#define WOFF_QKV 0u
#define WOFF_PROJ 12582912u               // 6144*2048
#define WOFF_FC   16777216u               // + 2048*2048
#define WOFF_MLP  33554432u               // + 2048*8192
#define WTOT      50331648u               // + 8192*2048
__device__ __half g_wt_hi[WTOT];          // weight hi plane [N,K] fp16
__device__ __half g_wt_lo[WTOT];          // weight lo plane (residual) fp16
__device__ __half g_act[(size_t)NTOK * E_];   // activations (ln1 -> ctx -> ln2)
__device__ __half g_fc [(size_t)NTOK * F_];   // fc hidden; also aliases qkv [NTOK*6144]

// ---------------------------------------------------------------------------
// PTX helpers (portable sm_80+ subset only)
// ---------------------------------------------------------------------------
__device__ __forceinline__ uint32_t smem_to_u32(const void* p) {
    uint32_t a;
    asm("{ .reg .u64 t; cvta.to.shared.u64 t, %1; cvt.u32.u64 %0, t; }" : "=r"(a) : "l"(p));
    return a;
}
__device__ __forceinline__ void cpa16(uint32_t dst, const void* src) {
    asm volatile("cp.async.cg.shared.global [%0], [%1], 16;" :: "r"(dst), "l"(src) : "memory");
}
#define CP_COMMIT() asm volatile("cp.async.commit_group;" ::: "memory")

__device__ __forceinline__ void ldsm4(uint32_t& r0, uint32_t& r1, uint32_t& r2, uint32_t& r3,
                                      uint32_t a) {
    asm volatile("ldmatrix.sync.aligned.m8n8.x4.shared.b16 {%0,%1,%2,%3}, [%4];"
                 : "=r"(r0), "=r"(r1), "=r"(r2), "=r"(r3) : "r"(a));
}
__device__ __forceinline__ void ldsm4t(uint32_t& r0, uint32_t& r1, uint32_t& r2, uint32_t& r3,
                                       uint32_t a) {
    asm volatile("ldmatrix.sync.aligned.m8n8.x4.trans.shared.b16 {%0,%1,%2,%3}, [%4];"
                 : "=r"(r0), "=r"(r1), "=r"(r2), "=r"(r3) : "r"(a));
}
// fp16 inputs, fp32 accumulate
__device__ __forceinline__ void mma16816h(float* c, const uint32_t* a, const uint32_t* b) {
    asm volatile(
        "mma.sync.aligned.m16n8k16.row.col.f32.f16.f16.f32 "
        "{%0,%1,%2,%3}, {%4,%5,%6,%7}, {%8,%9}, {%0,%1,%2,%3};"
        : "+f"(c[0]), "+f"(c[1]), "+f"(c[2]), "+f"(c[3])
        : "r"(a[0]), "r"(a[1]), "r"(a[2]), "r"(a[3]), "r"(b[0]), "r"(b[1]));
}

__device__ __forceinline__ void h2_store(float a, float b, __half* p, size_t idx) {
    __half2 h = __floats2half2_rn(a, b);
    *(__half2*)(p + idx) = h;
}
__device__ __forceinline__ uint32_t packh2(float a, float b) {
    __half2 h = __floats2half2_rn(a, b);
    return *reinterpret_cast<uint32_t*>(&h);
}

// ---------------------------------------------------------------------------
// Weight prep: W[K,N] fp32 -> Wh/Wl[N,K] fp16 (transpose + 2-term split)
// ---------------------------------------------------------------------------
__global__ __launch_bounds__(256) void wsplit_t_kernel(
    const float* __restrict__ W, __half* __restrict__ Th,
    __half* __restrict__ Tl, int K, int N)
{
    __shared__ float s[32][33];
    int n0 = blockIdx.x * 32, k0 = blockIdx.y * 32;
    int tx = threadIdx.x, ty = threadIdx.y;
#pragma unroll
    for (int j = 0; j < 4; j++)
        s[ty + j * 8][tx] = W[(size_t)(k0 + ty + j * 8) * N + n0 + tx];
    __syncthreads();
#pragma unroll
    for (int j = 0; j < 4; j++) {
        float v = s[tx][ty + j * 8];
        __half h = __float2half_rn(v);
        __half l = __float2half_rn(v - __half2float(h));
        size_t o = (size_t)(n0 + ty + j * 8) * K + k0 + tx;
        Th[o] = h; Tl[o] = l;
    }
}

// ---------------------------------------------------------------------------
// Block reduction (256 threads)
// ---------------------------------------------------------------------------
__device__ __forceinline__ float blk_reduce_sum(float v, float* sbuf) {
    int lane = threadIdx.x & 31, wid = threadIdx.x >> 5;
#pragma unroll
    for (int o = 16; o; o >>= 1) v += __shfl_xor_sync(0xffffffffu, v, o);
    if (lane == 0) sbuf[wid] = v;
    __syncthreads();
    if (threadIdx.x < 32) {
        float u = (threadIdx.x < 8) ? sbuf[threadIdx.x] : 0.f;
#pragma unroll
        for (int o = 4; o; o >>= 1) u += __shfl_xor_sync(0xffffffffu, u, o);
        if (threadIdx.x == 0) sbuf[0] = u;
    }
    __syncthreads();
    float r = sbuf[0];
    __syncthreads();
    return r;
}

// ---------------------------------------------------------------------------
// LayerNorm -> single fp16 plane
// ---------------------------------------------------------------------------
__global__ __launch_bounds__(256) void ln_kernel(
    const float* __restrict__ x, const float* __restrict__ w,
    const float* __restrict__ b, __half* __restrict__ oh)
{
    __shared__ float sbuf[8];
    size_t base = (size_t)blockIdx.x * E_;
    int t = threadIdx.x;

    float4 v0 = *(const float4*)(x + base + 4 * t);
    float4 v1 = *(const float4*)(x + base + 4 * t + 1024);
    float s = v0.x + v0.y + v0.z + v0.w + v1.x + v1.y + v1.z + v1.w;
    float mean = blk_reduce_sum(s, sbuf) * (1.f / E_);
    float d, sq = 0.f;
    d = v0.x - mean; sq += d * d;  d = v0.y - mean; sq += d * d;
    d = v0.z - mean; sq += d * d;  d = v0.w - mean; sq += d * d;
    d = v1.x - mean; sq += d * d;  d = v1.y - mean; sq += d * d;
    d = v1.z - mean; sq += d * d;  d = v1.w - mean; sq += d * d;
    float var = blk_reduce_sum(sq, sbuf) * (1.f / E_);
    float r = rsqrtf(var + 1e-5f);

    float4 w0 = *(const float4*)(w + 4 * t);
    float4 w1 = *(const float4*)(w + 4 * t + 1024);
    float4 b0 = *(const float4*)(b + 4 * t);
    float4 b1 = *(const float4*)(b + 4 * t + 1024);

    h2_store((v0.x - mean) * r * w0.x + b0.x, (v0.y - mean) * r * w0.y + b0.y, oh, base + 4 * t);
    h2_store((v0.z - mean) * r * w0.z + b0.z, (v0.w - mean) * r * w0.w + b0.w, oh, base + 4 * t + 2);
    h2_store((v1.x - mean) * r * w1.x + b1.x, (v1.y - mean) * r * w1.y + b1.y, oh, base + 4 * t + 1024);
    h2_store((v1.z - mean) * r * w1.z + b1.z, (v1.w - mean) * r * w1.w + b1.w, oh, base + 4 * t + 1026);
}

// ---------------------------------------------------------------------------
// HMMA GEMM: C[M,N] = A[M,K] @ (Wh+Wl)[N,K]^T   (fp16, 2-term weight split)
// CTA 128x256, 8 warps (2m x 4n), warp tile 64x64, 256 threads, BK=32, 3-stage.
// ---------------------------------------------------------------------------
#define EPI_HALF  0   // fp16 out = (acc + bias)
#define EPI_GELU  1   // fp16 out = gelu(acc + bias)
#define EPI_RES   2   // fp32 out = acc + bias + res

#define BM 128
#define BN 256
#define BK 32
#define ROWB 80
#define SA   0
#define SB_H 10240
#define SB_L 30720
#define STAGE_BYTES 51200
#define HMMA_SMEM (3 * STAGE_BYTES)   // 153600

__device__ __forceinline__ float gelu_tanh(float x) {
    float x3 = x * x * x;
    float t = tanhf(0.7978845608028654f * (x + 0.044715f * x3));
    return 0.5f * x * (1.f + t);
}

__device__ __forceinline__ void g2s_stage(
    uint32_t sb, const __half* __restrict__ A,
    const __half* __restrict__ Bh, const __half* __restrict__ Bl,
    int bm, int bn, int K, int k0, int tid)
{
    // A: 128 rows x 4 chunks = 512 chunks (2 iters of 256 thr)
#pragma unroll
    for (int it = 0; it < 2; it++) {
        int c = tid + it * 256;
        int row = c >> 2, ch = c & 3;
        uint32_t off = (uint32_t)row * ROWB + ch * 16;
        cpa16(sb + SA + off, A + (size_t)(bm + row) * K + k0 + ch * 8);
    }
    // B: 256 rows x 4 chunks per plane (4 iters, 2 planes)
#pragma unroll
    for (int it = 0; it < 4; it++) {
        int c = tid + it * 256;
        int row = c >> 2, ch = c & 3;
        uint32_t off = (uint32_t)row * ROWB + ch * 16;
        size_t gb = (size_t)(bn + row) * K + k0 + ch * 8;
        cpa16(sb + SB_H + off, Bh + gb);
        cpa16(sb + SB_L + off, Bl + gb);
    }
    CP_COMMIT();
}

template <int EPI>
__global__ __launch_bounds__(256, 1) void hmma_kernel(
    const __half* __restrict__ A,
    const __half* __restrict__ Bh, const __half* __restrict__ Bl,
    const float* __restrict__ bias, const float* __restrict__ res,
    float* __restrict__ Cf, __half* __restrict__ Ch,
    int M, int N, int K)
{
    extern __shared__ char smem[];
    uint32_t sb0 = smem_to_u32(smem);
    int tid = threadIdx.x;
    int wid = tid >> 5, lane = tid & 31;
    int wm = (wid & 1) * 64, wn = (wid >> 1) * 64;
    int bm = blockIdx.y * BM, bn = blockIdx.x * BN;

    float acc[4][8][4];
#pragma unroll
    for (int i = 0; i < 4; i++)
#pragma unroll
        for (int j = 0; j < 8; j++)
#pragma unroll
            for (int k = 0; k < 4; k++) acc[i][j][k] = 0.f;

    uint32_t a_off = (uint32_t)(wm + (lane & 15)) * ROWB + ((lane >> 4) * 16);
    uint32_t b_off = (uint32_t)(wn + (lane & 7) + ((lane >> 4) * 8)) * ROWB
                   + (((lane >> 3) & 1) * 16);

    g2s_stage(sb0,               A, Bh, Bl, bm, bn, K, 0,  tid);
    g2s_stage(sb0 + STAGE_BYTES, A, Bh, Bl, bm, bn, K, BK, tid);

    int nk = K / BK;
    for (int kt = 0; kt < nk; kt++) {
        asm volatile("cp.async.wait_group 1;" ::: "memory");
        __syncthreads();
        if (kt + 2 < nk)
            g2s_stage(sb0 + (uint32_t)((kt + 2) % 3) * STAGE_BYTES,
                      A, Bh, Bl, bm, bn, K, (kt + 2) * BK, tid);
        else
            CP_COMMIT();

        uint32_t st = sb0 + (uint32_t)(kt % 3) * STAGE_BYTES;
#pragma unroll
        for (int ks = 0; ks < 2; ks++) {
            uint32_t koff = (uint32_t)ks * 32;
            uint32_t ah[4][4];
#pragma unroll
            for (int mi = 0; mi < 4; mi++) {
                uint32_t ra = st + SA + a_off + (uint32_t)mi * (16 * ROWB) + koff;
                ldsm4(ah[mi][0], ah[mi][1], ah[mi][2], ah[mi][3], ra);
            }
#pragma unroll
            for (int ng = 0; ng < 4; ng++) {
                uint32_t bh[4], bl[4];
                uint32_t rb = st + SB_H + b_off + (uint32_t)ng * (16 * ROWB) + koff;
                ldsm4(bh[0], bh[1], bh[2], bh[3], rb);
                ldsm4(bl[0], bl[1], bl[2], bl[3], rb + (SB_L - SB_H));
#pragma unroll
                for (int mi = 0; mi < 4; mi++) {
#pragma unroll
                    for (int sub = 0; sub < 2; sub++) {
                        float* C = acc[mi][2 * ng + sub];
                        mma16816h(C, ah[mi], &bh[sub * 2]);
                        mma16816h(C, ah[mi], &bl[sub * 2]);
                    }
                }
            }
        }
    }

    int mrow = bm + wm + (lane >> 2);
    int ncol0 = (lane & 3) * 2;
#pragma unroll
    for (int mi = 0; mi < 4; mi++) {
        int m0 = mrow + mi * 16;
#pragma unroll
        for (int nf = 0; nf < 8; nf++) {
            int n0 = bn + wn + nf * 8 + ncol0;
            float b0 = bias[n0], b1 = bias[n0 + 1];
            float v00 = acc[mi][nf][0] + b0, v01 = acc[mi][nf][1] + b1;
            float v10 = acc[mi][nf][2] + b0, v11 = acc[mi][nf][3] + b1;
            size_t o0 = (size_t)m0 * N + n0;
            size_t o1 = (size_t)(m0 + 8) * N + n0;
            if (EPI == EPI_GELU) {
                h2_store(gelu_tanh(v00), gelu_tanh(v01), Ch, o0);
                h2_store(gelu_tanh(v10), gelu_tanh(v11), Ch, o1);
            } else if (EPI == EPI_HALF) {
                h2_store(v00, v01, Ch, o0);
                h2_store(v10, v11, Ch, o1);
            } else {
                float2 r0 = *(const float2*)(res + o0);
                float2 r1 = *(const float2*)(res + o1);
                v00 += r0.x; v01 += r0.y; v10 += r1.x; v11 += r1.y;
                float2 s0 = {v00, v01}, s1 = {v10, v11};
                *(float2*)(Cf + o0) = s0;
                *(float2*)(Cf + o1) = s1;
            }
        }
    }
}

// ---------------------------------------------------------------------------
// Flash attention on mma.sync (fp16 single product, causal).
// CTA: 128 q rows, 8 warps. kv tiles of 64, double-buffered.
// ---------------------------------------------------------------------------
#define AROW 272                       // 128 fp16 = 256B + 16 pad
#define AT_K 0
#define AT_V 17408
#define AT_STAGE 34816
#define AT_Q (2 * AT_STAGE)            // 69632
#define ATTN_SMEM (AT_Q + 128 * AROW)  // 104448

__device__ __forceinline__ void attn_load_kv(
    uint32_t st, const __half* __restrict__ qkv, int bb, int h, int k0, int tid)
{
#pragma unroll
    for (int it = 0; it < 4; it++) {
        int c = tid + it * 256;
        int row = c >> 4, ch = c & 15;
        uint32_t off = (uint32_t)row * AROW + ch * 16;
        size_t g = (size_t)(bb * S_ + k0 + row) * QKV_STRIDE + h * D_ + ch * 8;
        cpa16(st + AT_K + off, qkv + g + E_);
        cpa16(st + AT_V + off, qkv + g + 2 * E_);
    }
    CP_COMMIT();
}

__global__ __launch_bounds__(256, 1) void attn_mma_kernel(
    const __half* __restrict__ qkv, __half* __restrict__ ctx)
{
    extern __shared__ char smem[];
    uint32_t sb = smem_to_u32(smem);
    int tid = threadIdx.x;
    int wid = tid >> 5, lane = tid & 31;
    int q0 = blockIdx.x * 128;
    int h = blockIdx.y, bb = blockIdx.z;
    int wbase = wid * 16;

#pragma unroll
    for (int it = 0; it < 8; it++) {
        int c = tid + it * 256;
        int row = c >> 4, ch = c & 15;
        uint32_t off = (uint32_t)row * AROW + ch * 16;
        size_t g = (size_t)(bb * S_ + q0 + row) * QKV_STRIDE + h * D_ + ch * 8;
        cpa16(sb + AT_Q + off, qkv + g);
    }
    CP_COMMIT();
    attn_load_kv(sb, qkv, bb, h, 0, tid);

    uint32_t a_off = (uint32_t)(wbase + (lane & 15)) * AROW + ((lane >> 4) * 16);
    uint32_t b_off = (uint32_t)((lane & 7) + ((lane >> 4) * 8)) * AROW + (((lane >> 3) & 1) * 16);
    uint32_t v_off = (uint32_t)(lane & 15) * AROW + ((lane >> 4) * 8) * 2;

    const float SCL = 0.08838834764831845f * 1.4426950408889634f;
    int row_lo = q0 + wbase + (lane >> 2);
    int row_hi = row_lo + 8;

    float o[16][4];
#pragma unroll
    for (int i = 0; i < 16; i++)
#pragma unroll
        for (int j = 0; j < 4; j++) o[i][j] = 0.f;
    float m_lo = -1e30f, m_hi = -1e30f, l_lo = 0.f, l_hi = 0.f;

    int nt = q0 / 64 + 2;
    for (int t = 0; t < nt; t++) {
        uint32_t st = sb + (uint32_t)(t & 1) * AT_STAGE;
        if (t + 1 < nt) {
            attn_load_kv(sb + (uint32_t)((t + 1) & 1) * AT_STAGE, qkv, bb, h,
                         (t + 1) * 64, tid);
            asm volatile("cp.async.wait_group 1;" ::: "memory");
        } else {
            asm volatile("cp.async.wait_group 0;" ::: "memory");
        }
        __syncthreads();

        int k0 = t * 64;
        bool skip = (k0 > q0 + wbase + 15);
        if (!skip) {
            float sacc[8][4];
#pragma unroll
            for (int i = 0; i < 8; i++)
#pragma unroll
                for (int j = 0; j < 4; j++) sacc[i][j] = 0.f;

#pragma unroll
            for (int ks = 0; ks < 8; ks++) {
                uint32_t koff = (uint32_t)ks * 32;
                uint32_t qf[4];
                ldsm4(qf[0], qf[1], qf[2], qf[3], sb + AT_Q + a_off + koff);
#pragma unroll
                for (int g = 0; g < 4; g++) {
                    uint32_t kh[4];
                    uint32_t rb = st + AT_K + b_off + (uint32_t)g * (16 * AROW) + koff;
                    ldsm4(kh[0], kh[1], kh[2], kh[3], rb);
                    mma16816h(sacc[2 * g],     qf, &kh[0]);
                    mma16816h(sacc[2 * g + 1], qf, &kh[2]);
                }
            }

            bool needmask = (k0 + 63) > (q0 + wbase);
#pragma unroll
            for (int nf = 0; nf < 8; nf++) {
                int col = k0 + nf * 8 + (lane & 3) * 2;
                float s0 = sacc[nf][0] * SCL, s1 = sacc[nf][1] * SCL;
                float s2 = sacc[nf][2] * SCL, s3 = sacc[nf][3] * SCL;
                if (needmask) {
                    if (col     > row_lo) s0 = -1e30f;
                    if (col + 1 > row_lo) s1 = -1e30f;
                    if (col     > row_hi) s2 = -1e30f;
                    if (col + 1 > row_hi) s3 = -1e30f;
                }
                sacc[nf][0] = s0; sacc[nf][1] = s1; sacc[nf][2] = s2; sacc[nf][3] = s3;
            }

            float mx_lo = -1e30f, mx_hi = -1e30f;
#pragma unroll
            for (int nf = 0; nf < 8; nf++) {
                mx_lo = fmaxf(mx_lo, fmaxf(sacc[nf][0], sacc[nf][1]));
                mx_hi = fmaxf(mx_hi, fmaxf(sacc[nf][2], sacc[nf][3]));
            }
            mx_lo = fmaxf(mx_lo, __shfl_xor_sync(0xffffffffu, mx_lo, 1));
            mx_lo = fmaxf(mx_lo, __shfl_xor_sync(0xffffffffu, mx_lo, 2));
            mx_hi = fmaxf(mx_hi, __shfl_xor_sync(0xffffffffu, mx_hi, 1));
            mx_hi = fmaxf(mx_hi, __shfl_xor_sync(0xffffffffu, mx_hi, 2));

            float mn_lo = fmaxf(m_lo, mx_lo), mn_hi = fmaxf(m_hi, mx_hi);
            float al_lo = exp2f(m_lo - mn_lo), al_hi = exp2f(m_hi - mn_hi);
            m_lo = mn_lo; m_hi = mn_hi;

            float sum_lo = 0.f, sum_hi = 0.f;
#pragma unroll
            for (int nf = 0; nf < 8; nf++) {
                float p0 = exp2f(sacc[nf][0] - m_lo);
                float p1 = exp2f(sacc[nf][1] - m_lo);
                float p2 = exp2f(sacc[nf][2] - m_hi);
                float p3 = exp2f(sacc[nf][3] - m_hi);
                sum_lo += p0 + p1; sum_hi += p2 + p3;
                sacc[nf][0] = p0; sacc[nf][1] = p1; sacc[nf][2] = p2; sacc[nf][3] = p3;
            }
            sum_lo += __shfl_xor_sync(0xffffffffu, sum_lo, 1);
            sum_lo += __shfl_xor_sync(0xffffffffu, sum_lo, 2);
            sum_hi += __shfl_xor_sync(0xffffffffu, sum_hi, 1);
            sum_hi += __shfl_xor_sync(0xffffffffu, sum_hi, 2);
            l_lo = l_lo * al_lo + sum_lo;
            l_hi = l_hi * al_hi + sum_hi;

#pragma unroll
            for (int i = 0; i < 16; i++) {
                o[i][0] *= al_lo; o[i][1] *= al_lo;
                o[i][2] *= al_hi; o[i][3] *= al_hi;
            }

            // pack P into fp16 A-fragments
            uint32_t pa[4][4];
#pragma unroll
            for (int ks = 0; ks < 4; ks++) {
                pa[ks][0] = packh2(sacc[2 * ks][0],     sacc[2 * ks][1]);
                pa[ks][1] = packh2(sacc[2 * ks][2],     sacc[2 * ks][3]);
                pa[ks][2] = packh2(sacc[2 * ks + 1][0], sacc[2 * ks + 1][1]);
                pa[ks][3] = packh2(sacc[2 * ks + 1][2], sacc[2 * ks + 1][3]);
            }

            // O += P V, V via ldmatrix.trans
#pragma unroll
            for (int ks = 0; ks < 4; ks++) {
#pragma unroll
                for (int dg = 0; dg < 8; dg++) {
                    uint32_t vh[4];
                    uint32_t rv = st + AT_V + v_off + (uint32_t)ks * (16 * AROW) + dg * 32;
                    ldsm4t(vh[0], vh[1], vh[2], vh[3], rv);
                    mma16816h(o[2 * dg],     pa[ks], &vh[0]);
                    mma16816h(o[2 * dg + 1], pa[ks], &vh[2]);
                }
            }
        }
        __syncthreads();
    }

    float li_lo = 1.f / l_lo, li_hi = 1.f / l_hi;
    size_t base_lo = (size_t)(bb * S_ + row_lo) * E_ + h * D_;
    size_t base_hi = (size_t)(bb * S_ + row_hi) * E_ + h * D_;
#pragma unroll
    for (int dgf = 0; dgf < 16; dgf++) {
        int col = dgf * 8 + (lane & 3) * 2;
        h2_store(o[dgf][0] * li_lo, o[dgf][1] * li_lo, ctx, base_lo + col);
        h2_store(o[dgf][2] * li_hi, o[dgf][3] * li_hi, ctx, base_hi + col);
    }
}

// ---------------------------------------------------------------------------
// Launch
// ---------------------------------------------------------------------------
extern "C" void kernel_launch(void* const* d_in, const int* in_sizes, int n_in,
                              void* d_out, int out_size)
{
    const float* x            = (const float*)d_in[0];
    const float* ln1_w        = (const float*)d_in[1];
    const float* ln1_b        = (const float*)d_in[2];
    const float* c_attn_w     = (const float*)d_in[3];
    const float* c_attn_b     = (const float*)d_in[4];
    const float* c_proj_w     = (const float*)d_in[5];
    const float* c_proj_b     = (const float*)d_in[6];
    const float* ln2_w        = (const float*)d_in[7];
    const float* ln2_b        = (const float*)d_in[8];
    const float* c_fc_w       = (const float*)d_in[9];
    const float* c_fc_b       = (const float*)d_in[10];
    const float* c_mlp_proj_w = (const float*)d_in[11];
    const float* c_mlp_proj_b = (const float*)d_in[12];
    float* out = (float*)d_out;

    void *p_wh, *p_wl, *p_a, *p_f;
    cudaGetSymbolAddress(&p_wh, g_wt_hi);
    cudaGetSymbolAddress(&p_wl, g_wt_lo);
    cudaGetSymbolAddress(&p_a,  g_act);
    cudaGetSymbolAddress(&p_f,  g_fc);
    __half* wh = (__half*)p_wh;
    __half* wl = (__half*)p_wl;
    __half* act = (__half*)p_a;
    __half* fc  = (__half*)p_f;    // also qkv plane

    cudaFuncSetAttribute(attn_mma_kernel, cudaFuncAttributeMaxDynamicSharedMemorySize, ATTN_SMEM);
    cudaFuncSetAttribute(hmma_kernel<EPI_HALF>, cudaFuncAttributeMaxDynamicSharedMemorySize, HMMA_SMEM);
    cudaFuncSetAttribute(hmma_kernel<EPI_GELU>, cudaFuncAttributeMaxDynamicSharedMemorySize, HMMA_SMEM);
    cudaFuncSetAttribute(hmma_kernel<EPI_RES>,  cudaFuncAttributeMaxDynamicSharedMemorySize, HMMA_SMEM);

    dim3 tb(32, 8);
    wsplit_t_kernel<<<dim3(6144 / 32, 2048 / 32), tb>>>(c_attn_w,     wh + WOFF_QKV,  wl + WOFF_QKV,  2048, 6144);
    wsplit_t_kernel<<<dim3(2048 / 32, 2048 / 32), tb>>>(c_proj_w,     wh + WOFF_PROJ, wl + WOFF_PROJ, 2048, 2048);
    wsplit_t_kernel<<<dim3(8192 / 32, 2048 / 32), tb>>>(c_fc_w,       wh + WOFF_FC,   wl + WOFF_FC,   2048, 8192);
    wsplit_t_kernel<<<dim3(2048 / 32, 8192 / 32), tb>>>(c_mlp_proj_w, wh + WOFF_MLP,  wl + WOFF_MLP,  8192, 2048);

    // 1. ln1(x) -> act
    ln_kernel<<<NTOK, 256>>>(x, ln1_w, ln1_b, act);

    // 2. qkv = ln1 @ Wqkv + b -> fp16 plane (aliased into fc buffer)
    hmma_kernel<EPI_HALF><<<dim3(QKV_STRIDE / BN, NTOK / BM), 256, HMMA_SMEM>>>(
        act, wh + WOFF_QKV, wl + WOFF_QKV, c_attn_b, nullptr,
        nullptr, fc, NTOK, QKV_STRIDE, E_);

    // 3. attention (tensor-core) -> ctx (act buffer)
    attn_mma_kernel<<<dim3(S_ / 128, H_, B_), 256, ATTN_SMEM>>>(fc, act);

    // 4. x2 = ctx @ Wproj + b + x -> d_out (fp32)
    hmma_kernel<EPI_RES><<<dim3(E_ / BN, NTOK / BM), 256, HMMA_SMEM>>>(
        act, wh + WOFF_PROJ, wl + WOFF_PROJ, c_proj_b, x,
        out, nullptr, NTOK, E_, E_);

    // 5. ln2(x2) -> act
    ln_kernel<<<NTOK, 256>>>(out, ln2_w, ln2_b, act);

    // 6. fc = gelu(ln2 @ Wfc + b) -> fc plane (overwrites qkv; safe)
    hmma_kernel<EPI_GELU><<<dim3(F_ / BN, NTOK / BM), 256, HMMA_SMEM>>>(
        act, wh + WOFF_FC, wl + WOFF_FC, c_fc_b, nullptr,
        nullptr, fc, NTOK, F_, E_);

    // 7. out = fc @ Wmlp + b + x2 -> d_out (fp32, in-place residual)
    hmma_kernel<EPI_RES><<<dim3(E_ / BN, NTOK / BM), 256, HMMA_SMEM>>>(
        fc, wh + WOFF_MLP, wl + WOFF_MLP, c_mlp_proj_b, out,
        out, nullptr, NTOK, E_, F_);

    (void)in_sizes; (void)n_in; (void)out_size;
}

// round 14
// speedup vs baseline: 2.4075x; 1.6532x over previous
#include <cuda_runtime.h>
#include <cuda_fp16.h>
#include <math.h>
#include <stdint.h>

// Problem dims (fixed)
#define B_  4
#define S_  2048
#define E_  2048
#define H_  16
#define D_  128
#define F_  8192
#define NTOK (B_ * S_)
#define QKV_STRIDE (3 * E_)

// ---------------------------------------------------------------------------
// Scratch (device globals)
// ---------------------------------------------------------------------------
#define WOFF_QKV 0u
#define WOFF_PROJ 12582912u               // 6144*2048
#define WOFF_FC   16777216u               // + 2048*2048
#define WOFF_MLP  33554432u               // + 2048*8192
#define WTOT      50331648u               // + 8192*2048
__device__ __half g_wt [WTOT];            // weights [N,K] fp16 (single plane)
__device__ __half g_act[(size_t)NTOK * E_];   // activations (ln1 -> ctx -> ln2)
__device__ __half g_fc [(size_t)NTOK * F_];   // fc hidden; also aliases qkv [NTOK*6144]

// ---------------------------------------------------------------------------
// PTX helpers (portable sm_80+ subset only)
// ---------------------------------------------------------------------------
__device__ __forceinline__ uint32_t smem_to_u32(const void* p) {
    uint32_t a;
    asm("{ .reg .u64 t; cvta.to.shared.u64 t, %1; cvt.u32.u64 %0, t; }" : "=r"(a) : "l"(p));
    return a;
}
__device__ __forceinline__ void cpa16(uint32_t dst, const void* src) {
    asm volatile("cp.async.cg.shared.global [%0], [%1], 16;" :: "r"(dst), "l"(src) : "memory");
}
#define CP_COMMIT() asm volatile("cp.async.commit_group;" ::: "memory")

__device__ __forceinline__ void ldsm4(uint32_t& r0, uint32_t& r1, uint32_t& r2, uint32_t& r3,
                                      uint32_t a) {
    asm volatile("ldmatrix.sync.aligned.m8n8.x4.shared.b16 {%0,%1,%2,%3}, [%4];"
                 : "=r"(r0), "=r"(r1), "=r"(r2), "=r"(r3) : "r"(a));
}
__device__ __forceinline__ void ldsm4t(uint32_t& r0, uint32_t& r1, uint32_t& r2, uint32_t& r3,
                                       uint32_t a) {
    asm volatile("ldmatrix.sync.aligned.m8n8.x4.trans.shared.b16 {%0,%1,%2,%3}, [%4];"
                 : "=r"(r0), "=r"(r1), "=r"(r2), "=r"(r3) : "r"(a));
}
// fp16 inputs, fp32 accumulate
__device__ __forceinline__ void mma16816h(float* c, const uint32_t* a, const uint32_t* b) {
    asm volatile(
        "mma.sync.aligned.m16n8k16.row.col.f32.f16.f16.f32 "
        "{%0,%1,%2,%3}, {%4,%5,%6,%7}, {%8,%9}, {%0,%1,%2,%3};"
        : "+f"(c[0]), "+f"(c[1]), "+f"(c[2]), "+f"(c[3])
        : "r"(a[0]), "r"(a[1]), "r"(a[2]), "r"(a[3]), "r"(b[0]), "r"(b[1]));
}

__device__ __forceinline__ void h2_store(float a, float b, __half* p, size_t idx) {
    __half2 h = __floats2half2_rn(a, b);
    *(__half2*)(p + idx) = h;
}
__device__ __forceinline__ uint32_t packh2(float a, float b) {
    __half2 h = __floats2half2_rn(a, b);
    return *reinterpret_cast<uint32_t*>(&h);
}

// ---------------------------------------------------------------------------
// Weight prep: W[K,N] fp32 -> T[N,K] fp16 (transpose, single plane)
// ---------------------------------------------------------------------------
__global__ __launch_bounds__(256) void wsplit_t_kernel(
    const float* __restrict__ W, __half* __restrict__ Th, int K, int N)
{
    __shared__ float s[32][33];
    int n0 = blockIdx.x * 32, k0 = blockIdx.y * 32;
    int tx = threadIdx.x, ty = threadIdx.y;
#pragma unroll
    for (int j = 0; j < 4; j++)
        s[ty + j * 8][tx] = W[(size_t)(k0 + ty + j * 8) * N + n0 + tx];
    __syncthreads();
#pragma unroll
    for (int j = 0; j < 4; j++) {
        float v = s[tx][ty + j * 8];
        Th[(size_t)(n0 + ty + j * 8) * K + k0 + tx] = __float2half_rn(v);
    }
}

// ---------------------------------------------------------------------------
// Block reduction (256 threads)
// ---------------------------------------------------------------------------
__device__ __forceinline__ float blk_reduce_sum(float v, float* sbuf) {
    int lane = threadIdx.x & 31, wid = threadIdx.x >> 5;
#pragma unroll
    for (int o = 16; o; o >>= 1) v += __shfl_xor_sync(0xffffffffu, v, o);
    if (lane == 0) sbuf[wid] = v;
    __syncthreads();
    if (threadIdx.x < 32) {
        float u = (threadIdx.x < 8) ? sbuf[threadIdx.x] : 0.f;
#pragma unroll
        for (int o = 4; o; o >>= 1) u += __shfl_xor_sync(0xffffffffu, u, o);
        if (threadIdx.x == 0) sbuf[0] = u;
    }
    __syncthreads();
    float r = sbuf[0];
    __syncthreads();
    return r;
}

// ---------------------------------------------------------------------------
// LayerNorm -> single fp16 plane
// ---------------------------------------------------------------------------
__global__ __launch_bounds__(256) void ln_kernel(
    const float* __restrict__ x, const float* __restrict__ w,
    const float* __restrict__ b, __half* __restrict__ oh)
{
    __shared__ float sbuf[8];
    size_t base = (size_t)blockIdx.x * E_;
    int t = threadIdx.x;

    float4 v0 = *(const float4*)(x + base + 4 * t);
    float4 v1 = *(const float4*)(x + base + 4 * t + 1024);
    float s = v0.x + v0.y + v0.z + v0.w + v1.x + v1.y + v1.z + v1.w;
    float mean = blk_reduce_sum(s, sbuf) * (1.f / E_);
    float d, sq = 0.f;
    d = v0.x - mean; sq += d * d;  d = v0.y - mean; sq += d * d;
    d = v0.z - mean; sq += d * d;  d = v0.w - mean; sq += d * d;
    d = v1.x - mean; sq += d * d;  d = v1.y - mean; sq += d * d;
    d = v1.z - mean; sq += d * d;  d = v1.w - mean; sq += d * d;
    float var = blk_reduce_sum(sq, sbuf) * (1.f / E_);
    float r = rsqrtf(var + 1e-5f);

    float4 w0 = *(const float4*)(w + 4 * t);
    float4 w1 = *(const float4*)(w + 4 * t + 1024);
    float4 b0 = *(const float4*)(b + 4 * t);
    float4 b1 = *(const float4*)(b + 4 * t + 1024);

    h2_store((v0.x - mean) * r * w0.x + b0.x, (v0.y - mean) * r * w0.y + b0.y, oh, base + 4 * t);
    h2_store((v0.z - mean) * r * w0.z + b0.z, (v0.w - mean) * r * w0.w + b0.w, oh, base + 4 * t + 2);
    h2_store((v1.x - mean) * r * w1.x + b1.x, (v1.y - mean) * r * w1.y + b1.y, oh, base + 4 * t + 1024);
    h2_store((v1.z - mean) * r * w1.z + b1.z, (v1.w - mean) * r * w1.w + b1.w, oh, base + 4 * t + 1026);
}

// ---------------------------------------------------------------------------
// HMMA GEMM: C[M,N] = A[M,K] @ W[N,K]^T   (plain fp16, fp32 accum)
// CTA 128x256, 8 warps (2m x 4n), warp tile 64x64, 256 threads, BK=32, 3-stage.
// ---------------------------------------------------------------------------
#define EPI_HALF  0   // fp16 out = (acc + bias)
#define EPI_GELU  1   // fp16 out = gelu(acc + bias)
#define EPI_RES   2   // fp32 out = acc + bias + res

#define BM 128
#define BN 256
#define BK 32
#define ROWB 80
#define SA   0
#define SB   10240
#define STAGE_BYTES 30720
#define HMMA_SMEM (3 * STAGE_BYTES)   // 92160

__device__ __forceinline__ float gelu_tanh(float x) {
    float x3 = x * x * x;
    float t = tanhf(0.7978845608028654f * (x + 0.044715f * x3));
    return 0.5f * x * (1.f + t);
}

__device__ __forceinline__ void g2s_stage(
    uint32_t sb, const __half* __restrict__ A, const __half* __restrict__ Bw,
    int bm, int bn, int K, int k0, int tid)
{
    // A: 128 rows x 4 chunks = 512 chunks (2 iters of 256 thr)
#pragma unroll
    for (int it = 0; it < 2; it++) {
        int c = tid + it * 256;
        int row = c >> 2, ch = c & 3;
        uint32_t off = (uint32_t)row * ROWB + ch * 16;
        cpa16(sb + SA + off, A + (size_t)(bm + row) * K + k0 + ch * 8);
    }
    // B: 256 rows x 4 chunks = 1024 chunks (4 iters)
#pragma unroll
    for (int it = 0; it < 4; it++) {
        int c = tid + it * 256;
        int row = c >> 2, ch = c & 3;
        uint32_t off = (uint32_t)row * ROWB + ch * 16;
        cpa16(sb + SB + off, Bw + (size_t)(bn + row) * K + k0 + ch * 8);
    }
    CP_COMMIT();
}

template <int EPI>
__global__ __launch_bounds__(256, 1) void hmma_kernel(
    const __half* __restrict__ A, const __half* __restrict__ Bw,
    const float* __restrict__ bias, const float* __restrict__ res,
    float* __restrict__ Cf, __half* __restrict__ Ch,
    int M, int N, int K)
{
    extern __shared__ char smem[];
    uint32_t sb0 = smem_to_u32(smem);
    int tid = threadIdx.x;
    int wid = tid >> 5, lane = tid & 31;
    int wm = (wid & 1) * 64, wn = (wid >> 1) * 64;
    int bm = blockIdx.y * BM, bn = blockIdx.x * BN;

    float acc[4][8][4];
#pragma unroll
    for (int i = 0; i < 4; i++)
#pragma unroll
        for (int j = 0; j < 8; j++)
#pragma unroll
            for (int k = 0; k < 4; k++) acc[i][j][k] = 0.f;

    uint32_t a_off = (uint32_t)(wm + (lane & 15)) * ROWB + ((lane >> 4) * 16);
    uint32_t b_off = (uint32_t)(wn + (lane & 7) + ((lane >> 4) * 8)) * ROWB
                   + (((lane >> 3) & 1) * 16);

    g2s_stage(sb0,               A, Bw, bm, bn, K, 0,  tid);
    g2s_stage(sb0 + STAGE_BYTES, A, Bw, bm, bn, K, BK, tid);

    int nk = K / BK;
    for (int kt = 0; kt < nk; kt++) {
        asm volatile("cp.async.wait_group 1;" ::: "memory");
        __syncthreads();
        if (kt + 2 < nk)
            g2s_stage(sb0 + (uint32_t)((kt + 2) % 3) * STAGE_BYTES,
                      A, Bw, bm, bn, K, (kt + 2) * BK, tid);
        else
            CP_COMMIT();

        uint32_t st = sb0 + (uint32_t)(kt % 3) * STAGE_BYTES;
#pragma unroll
        for (int ks = 0; ks < 2; ks++) {
            uint32_t koff = (uint32_t)ks * 32;
            uint32_t ah[4][4];
#pragma unroll
            for (int mi = 0; mi < 4; mi++) {
                uint32_t ra = st + SA + a_off + (uint32_t)mi * (16 * ROWB) + koff;
                ldsm4(ah[mi][0], ah[mi][1], ah[mi][2], ah[mi][3], ra);
            }
#pragma unroll
            for (int ng = 0; ng < 4; ng++) {
                uint32_t bh[4];
                uint32_t rb = st + SB + b_off + (uint32_t)ng * (16 * ROWB) + koff;
                ldsm4(bh[0], bh[1], bh[2], bh[3], rb);
#pragma unroll
                for (int mi = 0; mi < 4; mi++) {
                    mma16816h(acc[mi][2 * ng],     ah[mi], &bh[0]);
                    mma16816h(acc[mi][2 * ng + 1], ah[mi], &bh[2]);
                }
            }
        }
    }

    int mrow = bm + wm + (lane >> 2);
    int ncol0 = (lane & 3) * 2;
#pragma unroll
    for (int mi = 0; mi < 4; mi++) {
        int m0 = mrow + mi * 16;
#pragma unroll
        for (int nf = 0; nf < 8; nf++) {
            int n0 = bn + wn + nf * 8 + ncol0;
            float b0 = bias[n0], b1 = bias[n0 + 1];
            float v00 = acc[mi][nf][0] + b0, v01 = acc[mi][nf][1] + b1;
            float v10 = acc[mi][nf][2] + b0, v11 = acc[mi][nf][3] + b1;
            size_t o0 = (size_t)m0 * N + n0;
            size_t o1 = (size_t)(m0 + 8) * N + n0;
            if (EPI == EPI_GELU) {
                h2_store(gelu_tanh(v00), gelu_tanh(v01), Ch, o0);
                h2_store(gelu_tanh(v10), gelu_tanh(v11), Ch, o1);
            } else if (EPI == EPI_HALF) {
                h2_store(v00, v01, Ch, o0);
                h2_store(v10, v11, Ch, o1);
            } else {
                float2 r0 = *(const float2*)(res + o0);
                float2 r1 = *(const float2*)(res + o1);
                v00 += r0.x; v01 += r0.y; v10 += r1.x; v11 += r1.y;
                float2 s0 = {v00, v01}, s1 = {v10, v11};
                *(float2*)(Cf + o0) = s0;
                *(float2*)(Cf + o1) = s1;
            }
        }
    }
}

// ---------------------------------------------------------------------------
// Flash attention on mma.sync (fp16, causal). Unchanged from R13.
// ---------------------------------------------------------------------------
#define AROW 272                       // 128 fp16 = 256B + 16 pad
#define AT_K 0
#define AT_V 17408
#define AT_STAGE 34816
#define AT_Q (2 * AT_STAGE)            // 69632
#define ATTN_SMEM (AT_Q + 128 * AROW)  // 104448

__device__ __forceinline__ void attn_load_kv(
    uint32_t st, const __half* __restrict__ qkv, int bb, int h, int k0, int tid)
{
#pragma unroll
    for (int it = 0; it < 4; it++) {
        int c = tid + it * 256;
        int row = c >> 4, ch = c & 15;
        uint32_t off = (uint32_t)row * AROW + ch * 16;
        size_t g = (size_t)(bb * S_ + k0 + row) * QKV_STRIDE + h * D_ + ch * 8;
        cpa16(st + AT_K + off, qkv + g + E_);
        cpa16(st + AT_V + off, qkv + g + 2 * E_);
    }
    CP_COMMIT();
}

__global__ __launch_bounds__(256, 1) void attn_mma_kernel(
    const __half* __restrict__ qkv, __half* __restrict__ ctx)
{
    extern __shared__ char smem[];
    uint32_t sb = smem_to_u32(smem);
    int tid = threadIdx.x;
    int wid = tid >> 5, lane = tid & 31;
    int q0 = blockIdx.x * 128;
    int h = blockIdx.y, bb = blockIdx.z;
    int wbase = wid * 16;

#pragma unroll
    for (int it = 0; it < 8; it++) {
        int c = tid + it * 256;
        int row = c >> 4, ch = c & 15;
        uint32_t off = (uint32_t)row * AROW + ch * 16;
        size_t g = (size_t)(bb * S_ + q0 + row) * QKV_STRIDE + h * D_ + ch * 8;
        cpa16(sb + AT_Q + off, qkv + g);
    }
    CP_COMMIT();
    attn_load_kv(sb, qkv, bb, h, 0, tid);

    uint32_t a_off = (uint32_t)(wbase + (lane & 15)) * AROW + ((lane >> 4) * 16);
    uint32_t b_off = (uint32_t)((lane & 7) + ((lane >> 4) * 8)) * AROW + (((lane >> 3) & 1) * 16);
    uint32_t v_off = (uint32_t)(lane & 15) * AROW + ((lane >> 4) * 8) * 2;

    const float SCL = 0.08838834764831845f * 1.4426950408889634f;
    int row_lo = q0 + wbase + (lane >> 2);
    int row_hi = row_lo + 8;

    float o[16][4];
#pragma unroll
    for (int i = 0; i < 16; i++)
#pragma unroll
        for (int j = 0; j < 4; j++) o[i][j] = 0.f;
    float m_lo = -1e30f, m_hi = -1e30f, l_lo = 0.f, l_hi = 0.f;

    int nt = q0 / 64 + 2;
    for (int t = 0; t < nt; t++) {
        uint32_t st = sb + (uint32_t)(t & 1) * AT_STAGE;
        if (t + 1 < nt) {
            attn_load_kv(sb + (uint32_t)((t + 1) & 1) * AT_STAGE, qkv, bb, h,
                         (t + 1) * 64, tid);
            asm volatile("cp.async.wait_group 1;" ::: "memory");
        } else {
            asm volatile("cp.async.wait_group 0;" ::: "memory");
        }
        __syncthreads();

        int k0 = t * 64;
        bool skip = (k0 > q0 + wbase + 15);
        if (!skip) {
            float sacc[8][4];
#pragma unroll
            for (int i = 0; i < 8; i++)
#pragma unroll
                for (int j = 0; j < 4; j++) sacc[i][j] = 0.f;

#pragma unroll
            for (int ks = 0; ks < 8; ks++) {
                uint32_t koff = (uint32_t)ks * 32;
                uint32_t qf[4];
                ldsm4(qf[0], qf[1], qf[2], qf[3], sb + AT_Q + a_off + koff);
#pragma unroll
                for (int g = 0; g < 4; g++) {
                    uint32_t kh[4];
                    uint32_t rb = st + AT_K + b_off + (uint32_t)g * (16 * AROW) + koff;
                    ldsm4(kh[0], kh[1], kh[2], kh[3], rb);
                    mma16816h(sacc[2 * g],     qf, &kh[0]);
                    mma16816h(sacc[2 * g + 1], qf, &kh[2]);
                }
            }

            bool needmask = (k0 + 63) > (q0 + wbase);
#pragma unroll
            for (int nf = 0; nf < 8; nf++) {
                int col = k0 + nf * 8 + (lane & 3) * 2;
                float s0 = sacc[nf][0] * SCL, s1 = sacc[nf][1] * SCL;
                float s2 = sacc[nf][2] * SCL, s3 = sacc[nf][3] * SCL;
                if (needmask) {
                    if (col     > row_lo) s0 = -1e30f;
                    if (col + 1 > row_lo) s1 = -1e30f;
                    if (col     > row_hi) s2 = -1e30f;
                    if (col + 1 > row_hi) s3 = -1e30f;
                }
                sacc[nf][0] = s0; sacc[nf][1] = s1; sacc[nf][2] = s2; sacc[nf][3] = s3;
            }

            float mx_lo = -1e30f, mx_hi = -1e30f;
#pragma unroll
            for (int nf = 0; nf < 8; nf++) {
                mx_lo = fmaxf(mx_lo, fmaxf(sacc[nf][0], sacc[nf][1]));
                mx_hi = fmaxf(mx_hi, fmaxf(sacc[nf][2], sacc[nf][3]));
            }
            mx_lo = fmaxf(mx_lo, __shfl_xor_sync(0xffffffffu, mx_lo, 1));
            mx_lo = fmaxf(mx_lo, __shfl_xor_sync(0xffffffffu, mx_lo, 2));
            mx_hi = fmaxf(mx_hi, __shfl_xor_sync(0xffffffffu, mx_hi, 1));
            mx_hi = fmaxf(mx_hi, __shfl_xor_sync(0xffffffffu, mx_hi, 2));

            float mn_lo = fmaxf(m_lo, mx_lo), mn_hi = fmaxf(m_hi, mx_hi);
            float al_lo = exp2f(m_lo - mn_lo), al_hi = exp2f(m_hi - mn_hi);
            m_lo = mn_lo; m_hi = mn_hi;

            float sum_lo = 0.f, sum_hi = 0.f;
#pragma unroll
            for (int nf = 0; nf < 8; nf++) {
                float p0 = exp2f(sacc[nf][0] - m_lo);
                float p1 = exp2f(sacc[nf][1] - m_lo);
                float p2 = exp2f(sacc[nf][2] - m_hi);
                float p3 = exp2f(sacc[nf][3] - m_hi);
                sum_lo += p0 + p1; sum_hi += p2 + p3;
                sacc[nf][0] = p0; sacc[nf][1] = p1; sacc[nf][2] = p2; sacc[nf][3] = p3;
            }
            sum_lo += __shfl_xor_sync(0xffffffffu, sum_lo, 1);
            sum_lo += __shfl_xor_sync(0xffffffffu, sum_lo, 2);
            sum_hi += __shfl_xor_sync(0xffffffffu, sum_hi, 1);
            sum_hi += __shfl_xor_sync(0xffffffffu, sum_hi, 2);
            l_lo = l_lo * al_lo + sum_lo;
            l_hi = l_hi * al_hi + sum_hi;

#pragma unroll
            for (int i = 0; i < 16; i++) {
                o[i][0] *= al_lo; o[i][1] *= al_lo;
                o[i][2] *= al_hi; o[i][3] *= al_hi;
            }

            uint32_t pa[4][4];
#pragma unroll
            for (int ks = 0; ks < 4; ks++) {
                pa[ks][0] = packh2(sacc[2 * ks][0],     sacc[2 * ks][1]);
                pa[ks][1] = packh2(sacc[2 * ks][2],     sacc[2 * ks][3]);
                pa[ks][2] = packh2(sacc[2 * ks + 1][0], sacc[2 * ks + 1][1]);
                pa[ks][3] = packh2(sacc[2 * ks + 1][2], sacc[2 * ks + 1][3]);
            }

#pragma unroll
            for (int ks = 0; ks < 4; ks++) {
#pragma unroll
                for (int dg = 0; dg < 8; dg++) {
                    uint32_t vh[4];
                    uint32_t rv = st + AT_V + v_off + (uint32_t)ks * (16 * AROW) + dg * 32;
                    ldsm4t(vh[0], vh[1], vh[2], vh[3], rv);
                    mma16816h(o[2 * dg],     pa[ks], &vh[0]);
                    mma16816h(o[2 * dg + 1], pa[ks], &vh[2]);
                }
            }
        }
        __syncthreads();
    }

    float li_lo = 1.f / l_lo, li_hi = 1.f / l_hi;
    size_t base_lo = (size_t)(bb * S_ + row_lo) * E_ + h * D_;
    size_t base_hi = (size_t)(bb * S_ + row_hi) * E_ + h * D_;
#pragma unroll
    for (int dgf = 0; dgf < 16; dgf++) {
        int col = dgf * 8 + (lane & 3) * 2;
        h2_store(o[dgf][0] * li_lo, o[dgf][1] * li_lo, ctx, base_lo + col);
        h2_store(o[dgf][2] * li_hi, o[dgf][3] * li_hi, ctx, base_hi + col);
    }
}

// ---------------------------------------------------------------------------
// Launch
// ---------------------------------------------------------------------------
extern "C" void kernel_launch(void* const* d_in, const int* in_sizes, int n_in,
                              void* d_out, int out_size)
{
    const float* x            = (const float*)d_in[0];
    const float* ln1_w        = (const float*)d_in[1];
    const float* ln1_b        = (const float*)d_in[2];
    const float* c_attn_w     = (const float*)d_in[3];
    const float* c_attn_b     = (const float*)d_in[4];
    const float* c_proj_w     = (const float*)d_in[5];
    const float* c_proj_b     = (const float*)d_in[6];
    const float* ln2_w        = (const float*)d_in[7];
    const float* ln2_b        = (const float*)d_in[8];
    const float* c_fc_w       = (const float*)d_in[9];
    const float* c_fc_b       = (const float*)d_in[10];
    const float* c_mlp_proj_w = (const float*)d_in[11];
    const float* c_mlp_proj_b = (const float*)d_in[12];
    float* out = (float*)d_out;

    void *p_w, *p_a, *p_f;
    cudaGetSymbolAddress(&p_w, g_wt);
    cudaGetSymbolAddress(&p_a, g_act);
    cudaGetSymbolAddress(&p_f, g_fc);
    __half* wt  = (__half*)p_w;
    __half* act = (__half*)p_a;
    __half* fc  = (__half*)p_f;    // also qkv plane

    cudaFuncSetAttribute(attn_mma_kernel, cudaFuncAttributeMaxDynamicSharedMemorySize, ATTN_SMEM);
    cudaFuncSetAttribute(hmma_kernel<EPI_HALF>, cudaFuncAttributeMaxDynamicSharedMemorySize, HMMA_SMEM);
    cudaFuncSetAttribute(hmma_kernel<EPI_GELU>, cudaFuncAttributeMaxDynamicSharedMemorySize, HMMA_SMEM);
    cudaFuncSetAttribute(hmma_kernel<EPI_RES>,  cudaFuncAttributeMaxDynamicSharedMemorySize, HMMA_SMEM);

    dim3 tb(32, 8);
    wsplit_t_kernel<<<dim3(6144 / 32, 2048 / 32), tb>>>(c_attn_w,     wt + WOFF_QKV,  2048, 6144);
    wsplit_t_kernel<<<dim3(2048 / 32, 2048 / 32), tb>>>(c_proj_w,     wt + WOFF_PROJ, 2048, 2048);
    wsplit_t_kernel<<<dim3(8192 / 32, 2048 / 32), tb>>>(c_fc_w,       wt + WOFF_FC,   2048, 8192);
    wsplit_t_kernel<<<dim3(2048 / 32, 8192 / 32), tb>>>(c_mlp_proj_w, wt + WOFF_MLP,  8192, 2048);

    // 1. ln1(x) -> act
    ln_kernel<<<NTOK, 256>>>(x, ln1_w, ln1_b, act);

    // 2. qkv = ln1 @ Wqkv + b -> fp16 plane (aliased into fc buffer)
    hmma_kernel<EPI_HALF><<<dim3(QKV_STRIDE / BN, NTOK / BM), 256, HMMA_SMEM>>>(
        act, wt + WOFF_QKV, c_attn_b, nullptr, nullptr, fc, NTOK, QKV_STRIDE, E_);

    // 3. attention (tensor-core) -> ctx (act buffer)
    attn_mma_kernel<<<dim3(S_ / 128, H_, B_), 256, ATTN_SMEM>>>(fc, act);

    // 4. x2 = ctx @ Wproj + b + x -> d_out (fp32)
    hmma_kernel<EPI_RES><<<dim3(E_ / BN, NTOK / BM), 256, HMMA_SMEM>>>(
        act, wt + WOFF_PROJ, c_proj_b, x, out, nullptr, NTOK, E_, E_);

    // 5. ln2(x2) -> act
    ln_kernel<<<NTOK, 256>>>(out, ln2_w, ln2_b, act);

    // 6. fc = gelu(ln2 @ Wfc + b) -> fc plane (overwrites qkv; safe)
    hmma_kernel<EPI_GELU><<<dim3(F_ / BN, NTOK / BM), 256, HMMA_SMEM>>>(
        act, wt + WOFF_FC, c_fc_b, nullptr, nullptr, fc, NTOK, F_, E_);

    // 7. out = fc @ Wmlp + b + x2 -> d_out (fp32, in-place residual)
    hmma_kernel<EPI_RES><<<dim3(E_ / BN, NTOK / BM), 256, HMMA_SMEM>>>(
        fc, wt + WOFF_MLP, c_mlp_proj_b, out, out, nullptr, NTOK, E_, F_);

    (void)in_sizes; (void)n_in; (void)out_size;
}

// round 15
// speedup vs baseline: 2.4083x; 1.0003x over previous
#include <cuda_runtime.h>
#include <cuda_fp16.h>
#include <math.h>
#include <stdint.h>

// Problem dims (fixed)
#define B_  4
#define S_  2048
#define E_  2048
#define H_  16
#define D_  128
#define F_  8192
#define NTOK (B_ * S_)
#define QKV_STRIDE (3 * E_)

// ---------------------------------------------------------------------------
// Scratch (device globals)
// ---------------------------------------------------------------------------
#define WOFF_QKV 0u
#define WOFF_PROJ 12582912u               // 6144*2048
#define WOFF_FC   16777216u               // + 2048*2048
#define WOFF_MLP  33554432u               // + 2048*8192
#define WTOT      50331648u               // + 8192*2048
__device__ __half g_wt [WTOT];            // weights [N,K] fp16 (single plane)
__device__ __half g_act[(size_t)NTOK * E_];   // activations (ln1 -> ctx -> ln2)
__device__ __half g_fc [(size_t)NTOK * F_];   // fc hidden; also aliases qkv [NTOK*6144]

// ---------------------------------------------------------------------------
// PTX helpers (portable sm_80+ subset only)
// ---------------------------------------------------------------------------
__device__ __forceinline__ uint32_t smem_to_u32(const void* p) {
    uint32_t a;
    asm("{ .reg .u64 t; cvta.to.shared.u64 t, %1; cvt.u32.u64 %0, t; }" : "=r"(a) : "l"(p));
    return a;
}
__device__ __forceinline__ void cpa16(uint32_t dst, const void* src) {
    asm volatile("cp.async.cg.shared.global [%0], [%1], 16;" :: "r"(dst), "l"(src) : "memory");
}
#define CP_COMMIT() asm volatile("cp.async.commit_group;" ::: "memory")

__device__ __forceinline__ void ldsm4(uint32_t& r0, uint32_t& r1, uint32_t& r2, uint32_t& r3,
                                      uint32_t a) {
    asm volatile("ldmatrix.sync.aligned.m8n8.x4.shared.b16 {%0,%1,%2,%3}, [%4];"
                 : "=r"(r0), "=r"(r1), "=r"(r2), "=r"(r3) : "r"(a));
}
__device__ __forceinline__ void ldsm4t(uint32_t& r0, uint32_t& r1, uint32_t& r2, uint32_t& r3,
                                       uint32_t a) {
    asm volatile("ldmatrix.sync.aligned.m8n8.x4.trans.shared.b16 {%0,%1,%2,%3}, [%4];"
                 : "=r"(r0), "=r"(r1), "=r"(r2), "=r"(r3) : "r"(a));
}
// fp16 inputs, fp32 accumulate
__device__ __forceinline__ void mma16816h(float* c, const uint32_t* a, const uint32_t* b) {
    asm volatile(
        "mma.sync.aligned.m16n8k16.row.col.f32.f16.f16.f32 "
        "{%0,%1,%2,%3}, {%4,%5,%6,%7}, {%8,%9}, {%0,%1,%2,%3};"
        : "+f"(c[0]), "+f"(c[1]), "+f"(c[2]), "+f"(c[3])
        : "r"(a[0]), "r"(a[1]), "r"(a[2]), "r"(a[3]), "r"(b[0]), "r"(b[1]));
}

__device__ __forceinline__ void h2_store(float a, float b, __half* p, size_t idx) {
    __half2 h = __floats2half2_rn(a, b);
    *(__half2*)(p + idx) = h;
}
__device__ __forceinline__ uint32_t packh2(float a, float b) {
    __half2 h = __floats2half2_rn(a, b);
    return *reinterpret_cast<uint32_t*>(&h);
}

// ---------------------------------------------------------------------------
// Weight prep: W[K,N] fp32 -> T[N,K] fp16 (transpose, single plane)
// ---------------------------------------------------------------------------
__global__ __launch_bounds__(256) void wsplit_t_kernel(
    const float* __restrict__ W, __half* __restrict__ Th, int K, int N)
{
    __shared__ float s[32][33];
    int n0 = blockIdx.x * 32, k0 = blockIdx.y * 32;
    int tx = threadIdx.x, ty = threadIdx.y;
#pragma unroll
    for (int j = 0; j < 4; j++)
        s[ty + j * 8][tx] = W[(size_t)(k0 + ty + j * 8) * N + n0 + tx];
    __syncthreads();
#pragma unroll
    for (int j = 0; j < 4; j++) {
        float v = s[tx][ty + j * 8];
        Th[(size_t)(n0 + ty + j * 8) * K + k0 + tx] = __float2half_rn(v);
    }
}

// ---------------------------------------------------------------------------
// Block reduction (256 threads)
// ---------------------------------------------------------------------------
__device__ __forceinline__ float blk_reduce_sum(float v, float* sbuf) {
    int lane = threadIdx.x & 31, wid = threadIdx.x >> 5;
#pragma unroll
    for (int o = 16; o; o >>= 1) v += __shfl_xor_sync(0xffffffffu, v, o);
    if (lane == 0) sbuf[wid] = v;
    __syncthreads();
    if (threadIdx.x < 32) {
        float u = (threadIdx.x < 8) ? sbuf[threadIdx.x] : 0.f;
#pragma unroll
        for (int o = 4; o; o >>= 1) u += __shfl_xor_sync(0xffffffffu, u, o);
        if (threadIdx.x == 0) sbuf[0] = u;
    }
    __syncthreads();
    float r = sbuf[0];
    __syncthreads();
    return r;
}

// ---------------------------------------------------------------------------
// LayerNorm -> single fp16 plane
// ---------------------------------------------------------------------------
__global__ __launch_bounds__(256) void ln_kernel(
    const float* __restrict__ x, const float* __restrict__ w,
    const float* __restrict__ b, __half* __restrict__ oh)
{
    __shared__ float sbuf[8];
    size_t base = (size_t)blockIdx.x * E_;
    int t = threadIdx.x;

    float4 v0 = *(const float4*)(x + base + 4 * t);
    float4 v1 = *(const float4*)(x + base + 4 * t + 1024);
    float s = v0.x + v0.y + v0.z + v0.w + v1.x + v1.y + v1.z + v1.w;
    float mean = blk_reduce_sum(s, sbuf) * (1.f / E_);
    float d, sq = 0.f;
    d = v0.x - mean; sq += d * d;  d = v0.y - mean; sq += d * d;
    d = v0.z - mean; sq += d * d;  d = v0.w - mean; sq += d * d;
    d = v1.x - mean; sq += d * d;  d = v1.y - mean; sq += d * d;
    d = v1.z - mean; sq += d * d;  d = v1.w - mean; sq += d * d;
    float var = blk_reduce_sum(sq, sbuf) * (1.f / E_);
    float r = rsqrtf(var + 1e-5f);

    float4 w0 = *(const float4*)(w + 4 * t);
    float4 w1 = *(const float4*)(w + 4 * t + 1024);
    float4 b0 = *(const float4*)(b + 4 * t);
    float4 b1 = *(const float4*)(b + 4 * t + 1024);

    h2_store((v0.x - mean) * r * w0.x + b0.x, (v0.y - mean) * r * w0.y + b0.y, oh, base + 4 * t);
    h2_store((v0.z - mean) * r * w0.z + b0.z, (v0.w - mean) * r * w0.w + b0.w, oh, base + 4 * t + 2);
    h2_store((v1.x - mean) * r * w1.x + b1.x, (v1.y - mean) * r * w1.y + b1.y, oh, base + 4 * t + 1024);
    h2_store((v1.z - mean) * r * w1.z + b1.z, (v1.w - mean) * r * w1.w + b1.w, oh, base + 4 * t + 1026);
}

// ---------------------------------------------------------------------------
// HMMA GEMM: C[M,N] = A[M,K] @ W[N,K]^T   (plain fp16, fp32 accum)
// CTA 128x256, 8 warps (2m x 4n), warp tile 64x64, 256 threads, BK=32, 3-stage.
// ---------------------------------------------------------------------------
#define EPI_HALF  0   // fp16 out = (acc + bias)
#define EPI_GELU  1   // fp16 out = gelu(acc + bias)
#define EPI_RES   2   // fp32 out = acc + bias + res

#define BM 128
#define BN 256
#define BK 32
#define ROWB 80
#define SA   0
#define SB   10240
#define STAGE_BYTES 30720
#define HMMA_SMEM (3 * STAGE_BYTES)   // 92160

__device__ __forceinline__ float gelu_tanh(float x) {
    float x3 = x * x * x;
    float t = tanhf(0.7978845608028654f * (x + 0.044715f * x3));
    return 0.5f * x * (1.f + t);
}

__device__ __forceinline__ void g2s_stage(
    uint32_t sb, const __half* __restrict__ A, const __half* __restrict__ Bw,
    int bm, int bn, int K, int k0, int tid)
{
    // A: 128 rows x 4 chunks = 512 chunks (2 iters of 256 thr)
#pragma unroll
    for (int it = 0; it < 2; it++) {
        int c = tid + it * 256;
        int row = c >> 2, ch = c & 3;
        uint32_t off = (uint32_t)row * ROWB + ch * 16;
        cpa16(sb + SA + off, A + (size_t)(bm + row) * K + k0 + ch * 8);
    }
    // B: 256 rows x 4 chunks = 1024 chunks (4 iters)
#pragma unroll
    for (int it = 0; it < 4; it++) {
        int c = tid + it * 256;
        int row = c >> 2, ch = c & 3;
        uint32_t off = (uint32_t)row * ROWB + ch * 16;
        cpa16(sb + SB + off, Bw + (size_t)(bn + row) * K + k0 + ch * 8);
    }
    CP_COMMIT();
}

template <int EPI>
__global__ __launch_bounds__(256, 1) void hmma_kernel(
    const __half* __restrict__ A, const __half* __restrict__ Bw,
    const float* __restrict__ bias, const float* __restrict__ res,
    float* __restrict__ Cf, __half* __restrict__ Ch,
    int M, int N, int K)
{
    extern __shared__ char smem[];
    uint32_t sb0 = smem_to_u32(smem);
    int tid = threadIdx.x;
    int wid = tid >> 5, lane = tid & 31;
    int wm = (wid & 1) * 64, wn = (wid >> 1) * 64;
    int bm = blockIdx.y * BM, bn = blockIdx.x * BN;

    float acc[4][8][4];
#pragma unroll
    for (int i = 0; i < 4; i++)
#pragma unroll
        for (int j = 0; j < 8; j++)
#pragma unroll
            for (int k = 0; k < 4; k++) acc[i][j][k] = 0.f;

    uint32_t a_off = (uint32_t)(wm + (lane & 15)) * ROWB + ((lane >> 4) * 16);
    uint32_t b_off = (uint32_t)(wn + (lane & 7) + ((lane >> 4) * 8)) * ROWB
                   + (((lane >> 3) & 1) * 16);

    g2s_stage(sb0,               A, Bw, bm, bn, K, 0,  tid);
    g2s_stage(sb0 + STAGE_BYTES, A, Bw, bm, bn, K, BK, tid);

    int nk = K / BK;
    for (int kt = 0; kt < nk; kt++) {
        asm volatile("cp.async.wait_group 1;" ::: "memory");
        __syncthreads();
        if (kt + 2 < nk)
            g2s_stage(sb0 + (uint32_t)((kt + 2) % 3) * STAGE_BYTES,
                      A, Bw, bm, bn, K, (kt + 2) * BK, tid);
        else
            CP_COMMIT();

        uint32_t st = sb0 + (uint32_t)(kt % 3) * STAGE_BYTES;
#pragma unroll
        for (int ks = 0; ks < 2; ks++) {
            uint32_t koff = (uint32_t)ks * 32;
            uint32_t ah[4][4];
#pragma unroll
            for (int mi = 0; mi < 4; mi++) {
                uint32_t ra = st + SA + a_off + (uint32_t)mi * (16 * ROWB) + koff;
                ldsm4(ah[mi][0], ah[mi][1], ah[mi][2], ah[mi][3], ra);
            }
#pragma unroll
            for (int ng = 0; ng < 4; ng++) {
                uint32_t bh[4];
                uint32_t rb = st + SB + b_off + (uint32_t)ng * (16 * ROWB) + koff;
                ldsm4(bh[0], bh[1], bh[2], bh[3], rb);
#pragma unroll
                for (int mi = 0; mi < 4; mi++) {
                    mma16816h(acc[mi][2 * ng],     ah[mi], &bh[0]);
                    mma16816h(acc[mi][2 * ng + 1], ah[mi], &bh[2]);
                }
            }
        }
    }

    int mrow = bm + wm + (lane >> 2);
    int ncol0 = (lane & 3) * 2;
#pragma unroll
    for (int mi = 0; mi < 4; mi++) {
        int m0 = mrow + mi * 16;
#pragma unroll
        for (int nf = 0; nf < 8; nf++) {
            int n0 = bn + wn + nf * 8 + ncol0;
            float b0 = bias[n0], b1 = bias[n0 + 1];
            float v00 = acc[mi][nf][0] + b0, v01 = acc[mi][nf][1] + b1;
            float v10 = acc[mi][nf][2] + b0, v11 = acc[mi][nf][3] + b1;
            size_t o0 = (size_t)m0 * N + n0;
            size_t o1 = (size_t)(m0 + 8) * N + n0;
            if (EPI == EPI_GELU) {
                h2_store(gelu_tanh(v00), gelu_tanh(v01), Ch, o0);
                h2_store(gelu_tanh(v10), gelu_tanh(v11), Ch, o1);
            } else if (EPI == EPI_HALF) {
                h2_store(v00, v01, Ch, o0);
                h2_store(v10, v11, Ch, o1);
            } else {
                float2 r0 = *(const float2*)(res + o0);
                float2 r1 = *(const float2*)(res + o1);
                v00 += r0.x; v01 += r0.y; v10 += r1.x; v11 += r1.y;
                float2 s0 = {v00, v01}, s1 = {v10, v11};
                *(float2*)(Cf + o0) = s0;
                *(float2*)(Cf + o1) = s1;
            }
        }
    }
}

// ---------------------------------------------------------------------------
// Flash attention on mma.sync (fp16, causal). Unchanged from R13.
// ---------------------------------------------------------------------------
#define AROW 272                       // 128 fp16 = 256B + 16 pad
#define AT_K 0
#define AT_V 17408
#define AT_STAGE 34816
#define AT_Q (2 * AT_STAGE)            // 69632
#define ATTN_SMEM (AT_Q + 128 * AROW)  // 104448

__device__ __forceinline__ void attn_load_kv(
    uint32_t st, const __half* __restrict__ qkv, int bb, int h, int k0, int tid)
{
#pragma unroll
    for (int it = 0; it < 4; it++) {
        int c = tid + it * 256;
        int row = c >> 4, ch = c & 15;
        uint32_t off = (uint32_t)row * AROW + ch * 16;
        size_t g = (size_t)(bb * S_ + k0 + row) * QKV_STRIDE + h * D_ + ch * 8;
        cpa16(st + AT_K + off, qkv + g + E_);
        cpa16(st + AT_V + off, qkv + g + 2 * E_);
    }
    CP_COMMIT();
}

__global__ __launch_bounds__(256, 1) void attn_mma_kernel(
    const __half* __restrict__ qkv, __half* __restrict__ ctx)
{
    extern __shared__ char smem[];
    uint32_t sb = smem_to_u32(smem);
    int tid = threadIdx.x;
    int wid = tid >> 5, lane = tid & 31;
    int q0 = blockIdx.x * 128;
    int h = blockIdx.y, bb = blockIdx.z;
    int wbase = wid * 16;

#pragma unroll
    for (int it = 0; it < 8; it++) {
        int c = tid + it * 256;
        int row = c >> 4, ch = c & 15;
        uint32_t off = (uint32_t)row * AROW + ch * 16;
        size_t g = (size_t)(bb * S_ + q0 + row) * QKV_STRIDE + h * D_ + ch * 8;
        cpa16(sb + AT_Q + off, qkv + g);
    }
    CP_COMMIT();
    attn_load_kv(sb, qkv, bb, h, 0, tid);

    uint32_t a_off = (uint32_t)(wbase + (lane & 15)) * AROW + ((lane >> 4) * 16);
    uint32_t b_off = (uint32_t)((lane & 7) + ((lane >> 4) * 8)) * AROW + (((lane >> 3) & 1) * 16);
    uint32_t v_off = (uint32_t)(lane & 15) * AROW + ((lane >> 4) * 8) * 2;

    const float SCL = 0.08838834764831845f * 1.4426950408889634f;
    int row_lo = q0 + wbase + (lane >> 2);
    int row_hi = row_lo + 8;

    float o[16][4];
#pragma unroll
    for (int i = 0; i < 16; i++)
#pragma unroll
        for (int j = 0; j < 4; j++) o[i][j] = 0.f;
    float m_lo = -1e30f, m_hi = -1e30f, l_lo = 0.f, l_hi = 0.f;

    int nt = q0 / 64 + 2;
    for (int t = 0; t < nt; t++) {
        uint32_t st = sb + (uint32_t)(t & 1) * AT_STAGE;
        if (t + 1 < nt) {
            attn_load_kv(sb + (uint32_t)((t + 1) & 1) * AT_STAGE, qkv, bb, h,
                         (t + 1) * 64, tid);
            asm volatile("cp.async.wait_group 1;" ::: "memory");
        } else {
            asm volatile("cp.async.wait_group 0;" ::: "memory");
        }
        __syncthreads();

        int k0 = t * 64;
        bool skip = (k0 > q0 + wbase + 15);
        if (!skip) {
            float sacc[8][4];
#pragma unroll
            for (int i = 0; i < 8; i++)
#pragma unroll
                for (int j = 0; j < 4; j++) sacc[i][j] = 0.f;

#pragma unroll
            for (int ks = 0; ks < 8; ks++) {
                uint32_t koff = (uint32_t)ks * 32;
                uint32_t qf[4];
                ldsm4(qf[0], qf[1], qf[2], qf[3], sb + AT_Q + a_off + koff);
#pragma unroll
                for (int g = 0; g < 4; g++) {
                    uint32_t kh[4];
                    uint32_t rb = st + AT_K + b_off + (uint32_t)g * (16 * AROW) + koff;
                    ldsm4(kh[0], kh[1], kh[2], kh[3], rb);
                    mma16816h(sacc[2 * g],     qf, &kh[0]);
                    mma16816h(sacc[2 * g + 1], qf, &kh[2]);
                }
            }

            bool needmask = (k0 + 63) > (q0 + wbase);
#pragma unroll
            for (int nf = 0; nf < 8; nf++) {
                int col = k0 + nf * 8 + (lane & 3) * 2;
                float s0 = sacc[nf][0] * SCL, s1 = sacc[nf][1] * SCL;
                float s2 = sacc[nf][2] * SCL, s3 = sacc[nf][3] * SCL;
                if (needmask) {
                    if (col     > row_lo) s0 = -1e30f;
                    if (col + 1 > row_lo) s1 = -1e30f;
                    if (col     > row_hi) s2 = -1e30f;
                    if (col + 1 > row_hi) s3 = -1e30f;
                }
                sacc[nf][0] = s0; sacc[nf][1] = s1; sacc[nf][2] = s2; sacc[nf][3] = s3;
            }

            float mx_lo = -1e30f, mx_hi = -1e30f;
#pragma unroll
            for (int nf = 0; nf < 8; nf++) {
                mx_lo = fmaxf(mx_lo, fmaxf(sacc[nf][0], sacc[nf][1]));
                mx_hi = fmaxf(mx_hi, fmaxf(sacc[nf][2], sacc[nf][3]));
            }
            mx_lo = fmaxf(mx_lo, __shfl_xor_sync(0xffffffffu, mx_lo, 1));
            mx_lo = fmaxf(mx_lo, __shfl_xor_sync(0xffffffffu, mx_lo, 2));
            mx_hi = fmaxf(mx_hi, __shfl_xor_sync(0xffffffffu, mx_hi, 1));
            mx_hi = fmaxf(mx_hi, __shfl_xor_sync(0xffffffffu, mx_hi, 2));

            float mn_lo = fmaxf(m_lo, mx_lo), mn_hi = fmaxf(m_hi, mx_hi);
            float al_lo = exp2f(m_lo - mn_lo), al_hi = exp2f(m_hi - mn_hi);
            m_lo = mn_lo; m_hi = mn_hi;

            float sum_lo = 0.f, sum_hi = 0.f;
#pragma unroll
            for (int nf = 0; nf < 8; nf++) {
                float p0 = exp2f(sacc[nf][0] - m_lo);
                float p1 = exp2f(sacc[nf][1] - m_lo);
                float p2 = exp2f(sacc[nf][2] - m_hi);
                float p3 = exp2f(sacc[nf][3] - m_hi);
                sum_lo += p0 + p1; sum_hi += p2 + p3;
                sacc[nf][0] = p0; sacc[nf][1] = p1; sacc[nf][2] = p2; sacc[nf][3] = p3;
            }
            sum_lo += __shfl_xor_sync(0xffffffffu, sum_lo, 1);
            sum_lo += __shfl_xor_sync(0xffffffffu, sum_lo, 2);
            sum_hi += __shfl_xor_sync(0xffffffffu, sum_hi, 1);
            sum_hi += __shfl_xor_sync(0xffffffffu, sum_hi, 2);
            l_lo = l_lo * al_lo + sum_lo;
            l_hi = l_hi * al_hi + sum_hi;

#pragma unroll
            for (int i = 0; i < 16; i++) {
                o[i][0] *= al_lo; o[i][1] *= al_lo;
                o[i][2] *= al_hi; o[i][3] *= al_hi;
            }

            uint32_t pa[4][4];
#pragma unroll
            for (int ks = 0; ks < 4; ks++) {
                pa[ks][0] = packh2(sacc[2 * ks][0],     sacc[2 * ks][1]);
                pa[ks][1] = packh2(sacc[2 * ks][2],     sacc[2 * ks][3]);
                pa[ks][2] = packh2(sacc[2 * ks + 1][0], sacc[2 * ks + 1][1]);
                pa[ks][3] = packh2(sacc[2 * ks + 1][2], sacc[2 * ks + 1][3]);
            }

#pragma unroll
            for (int ks = 0; ks < 4; ks++) {
#pragma unroll
                for (int dg = 0; dg < 8; dg++) {
                    uint32_t vh[4];
                    uint32_t rv = st + AT_V + v_off + (uint32_t)ks * (16 * AROW) + dg * 32;
                    ldsm4t(vh[0], vh[1], vh[2], vh[3], rv);
                    mma16816h(o[2 * dg],     pa[ks], &vh[0]);
                    mma16816h(o[2 * dg + 1], pa[ks], &vh[2]);
                }
            }
        }
        __syncthreads();
    }

    float li_lo = 1.f / l_lo, li_hi = 1.f / l_hi;
    size_t base_lo = (size_t)(bb * S_ + row_lo) * E_ + h * D_;
    size_t base_hi = (size_t)(bb * S_ + row_hi) * E_ + h * D_;
#pragma unroll
    for (int dgf = 0; dgf < 16; dgf++) {
        int col = dgf * 8 + (lane & 3) * 2;
        h2_store(o[dgf][0] * li_lo, o[dgf][1] * li_lo, ctx, base_lo + col);
        h2_store(o[dgf][2] * li_hi, o[dgf][3] * li_hi, ctx, base_hi + col);
    }
}

// ---------------------------------------------------------------------------
// Launch
// ---------------------------------------------------------------------------
extern "C" void kernel_launch(void* const* d_in, const int* in_sizes, int n_in,
                              void* d_out, int out_size)
{
    const float* x            = (const float*)d_in[0];
    const float* ln1_w        = (const float*)d_in[1];
    const float* ln1_b        = (const float*)d_in[2];
    const float* c_attn_w     = (const float*)d_in[3];
    const float* c_attn_b     = (const float*)d_in[4];
    const float* c_proj_w     = (const float*)d_in[5];
    const float* c_proj_b     = (const float*)d_in[6];
    const float* ln2_w        = (const float*)d_in[7];
    const float* ln2_b        = (const float*)d_in[8];
    const float* c_fc_w       = (const float*)d_in[9];
    const float* c_fc_b       = (const float*)d_in[10];
    const float* c_mlp_proj_w = (const float*)d_in[11];
    const float* c_mlp_proj_b = (const float*)d_in[12];
    float* out = (float*)d_out;

    void *p_w, *p_a, *p_f;
    cudaGetSymbolAddress(&p_w, g_wt);
    cudaGetSymbolAddress(&p_a, g_act);
    cudaGetSymbolAddress(&p_f, g_fc);
    __half* wt  = (__half*)p_w;
    __half* act = (__half*)p_a;
    __half* fc  = (__half*)p_f;    // also qkv plane

    cudaFuncSetAttribute(attn_mma_kernel, cudaFuncAttributeMaxDynamicSharedMemorySize, ATTN_SMEM);
    cudaFuncSetAttribute(hmma_kernel<EPI_HALF>, cudaFuncAttributeMaxDynamicSharedMemorySize, HMMA_SMEM);
    cudaFuncSetAttribute(hmma_kernel<EPI_GELU>, cudaFuncAttributeMaxDynamicSharedMemorySize, HMMA_SMEM);
    cudaFuncSetAttribute(hmma_kernel<EPI_RES>,  cudaFuncAttributeMaxDynamicSharedMemorySize, HMMA_SMEM);

    dim3 tb(32, 8);
    wsplit_t_kernel<<<dim3(6144 / 32, 2048 / 32), tb>>>(c_attn_w,     wt + WOFF_QKV,  2048, 6144);
    wsplit_t_kernel<<<dim3(2048 / 32, 2048 / 32), tb>>>(c_proj_w,     wt + WOFF_PROJ, 2048, 2048);
    wsplit_t_kernel<<<dim3(8192 / 32, 2048 / 32), tb>>>(c_fc_w,       wt + WOFF_FC,   2048, 8192);
    wsplit_t_kernel<<<dim3(2048 / 32, 8192 / 32), tb>>>(c_mlp_proj_w, wt + WOFF_MLP,  8192, 2048);

    // 1. ln1(x) -> act
    ln_kernel<<<NTOK, 256>>>(x, ln1_w, ln1_b, act);

    // 2. qkv = ln1 @ Wqkv + b -> fp16 plane (aliased into fc buffer)
    hmma_kernel<EPI_HALF><<<dim3(QKV_STRIDE / BN, NTOK / BM), 256, HMMA_SMEM>>>(
        act, wt + WOFF_QKV, c_attn_b, nullptr, nullptr, fc, NTOK, QKV_STRIDE, E_);

    // 3. attention (tensor-core) -> ctx (act buffer)
    attn_mma_kernel<<<dim3(S_ / 128, H_, B_), 256, ATTN_SMEM>>>(fc, act);

    // 4. x2 = ctx @ Wproj + b + x -> d_out (fp32)
    hmma_kernel<EPI_RES><<<dim3(E_ / BN, NTOK / BM), 256, HMMA_SMEM>>>(
        act, wt + WOFF_PROJ, c_proj_b, x, out, nullptr, NTOK, E_, E_);

    // 5. ln2(x2) -> act
    ln_kernel<<<NTOK, 256>>>(out, ln2_w, ln2_b, act);

    // 6. fc = gelu(ln2 @ Wfc + b) -> fc plane (overwrites qkv; safe)
    hmma_kernel<EPI_GELU><<<dim3(F_ / BN, NTOK / BM), 256, HMMA_SMEM>>>(
        act, wt + WOFF_FC, c_fc_b, nullptr, nullptr, fc, NTOK, F_, E_);

    // 7. out = fc @ Wmlp + b + x2 -> d_out (fp32, in-place residual)
    hmma_kernel<EPI_RES><<<dim3(E_ / BN, NTOK / BM), 256, HMMA_SMEM>>>(
        fc, wt + WOFF_MLP, c_mlp_proj_b, out, out, nullptr, NTOK, E_, F_);

    (void)in_sizes; (void)n_in; (void)out_size;
}